// round 13
// baseline (speedup 1.0000x reference)
#include <cuda_runtime.h>
#include <math.h>

#define S_LEN 2048
#define DIM   2048
#define NH    32
#define NKV   8
#define HD    64
#define NREP  4           // NH / NKV
#define ATT_SCALE 0.125f  // 1/sqrt(64)

// ---------------- scratch (device globals; no allocation allowed) ----------
__device__ float g_q[S_LEN * NH * HD];     // 16 MB
__device__ float g_k[S_LEN * NKV * HD];    // 4 MB
__device__ float g_v[S_LEN * NKV * HD];    // 4 MB
__device__ float g_attn[S_LEN * NH * HD];  // 16 MB

__device__ __forceinline__ unsigned f2tf(float f) {
    unsigned r;
    asm("cvt.rna.tf32.f32 %0, %1;" : "=r"(r) : "f"(f));
    return r;
}
__device__ __forceinline__ float ftf(float f) {
    return __uint_as_float(f2tf(f));
}

__device__ __forceinline__ void cpasync16(void* smem_ptr, const void* gptr) {
    unsigned s = (unsigned)__cvta_generic_to_shared(smem_ptr);
    asm volatile("cp.async.cg.shared.global [%0], [%1], 16;\n" :: "r"(s), "l"(gptr));
}
__device__ __forceinline__ void cp_commit() {
    asm volatile("cp.async.commit_group;\n");
}
__device__ __forceinline__ void cp_wait0() {
    asm volatile("cp.async.wait_group 0;\n");
}
__device__ __forceinline__ void cp_wait1() {
    asm volatile("cp.async.wait_group 1;\n");
}

// ---------------- TF32 tensor-core GEMM (in-smem conversion) ----------------
// C[M,N] = A[M,K] @ B[N,K]^T + bias[N]
// 128x128 block tile, BK=32, 3-stage cp.async, 8 warps (2x4), warp tile 64x32.
// After each tile wait, the stage is converted to tf32 IN PLACE (1 CVT per
// element) so the mma fragment loads are pure LDS.
// Epilogue modes: 0 = plain, 1 = fused RoPE (tf32-rounded), 2 = tf32-rounded.
#define GSTR  36
#define TILEW (128 * GSTR)
#define NSTG  3
#define ESTR  132   // epilogue staging stride

__device__ __forceinline__ void gemm_core(
    const float* __restrict__ A, const float* __restrict__ B,
    const float* __restrict__ bias, float* __restrict__ C,
    int N, int K, int m0, int n0, float* sm, int mode,
    const float* __restrict__ rope_g)
{
    float* As = sm;
    float* Bs = sm + NSTG * TILEW;

    const int tid  = threadIdx.x;
    const int lane = tid & 31;
    const int w    = tid >> 5;
    const int mw   = (w >> 2) * 64;
    const int nw   = (w & 3) * 32;
    const int g    = lane >> 2;
    const int t    = lane & 3;

    const int lr = tid >> 3;
    const int lc = (tid & 7) << 2;

    float acc[4][4][4];
#pragma unroll
    for (int mt = 0; mt < 4; mt++)
#pragma unroll
        for (int nt = 0; nt < 4; nt++)
#pragma unroll
            for (int r = 0; r < 4; r++) acc[mt][nt][r] = 0.f;

    const int ntiles = K >> 5;

#pragma unroll
    for (int p = 0; p < 2; p++) {
        float* ad = As + p * TILEW;
        float* bd = Bs + p * TILEW;
        const int k0 = p << 5;
#pragma unroll
        for (int i = 0; i < 4; i++) {
            int r = lr + i * 32;
            cpasync16(&ad[r * GSTR + lc], &A[(m0 + r) * K + k0 + lc]);
            cpasync16(&bd[r * GSTR + lc], &B[(n0 + r) * K + k0 + lc]);
        }
        cp_commit();
    }

    int st = 0;
    for (int kt = 0; kt < ntiles; kt++) {
        if (kt + 1 < ntiles) cp_wait1(); else cp_wait0();
        __syncthreads();

        float* ac = As + st * TILEW;
        float* bc = Bs + st * TILEW;

        // ---- in-place tf32 conversion of the arrived stage (1 CVT/elem) ----
#pragma unroll
        for (int i = 0; i < 4; i++) {
            int r = lr + i * 32;
            float4 va = *(float4*)&ac[r * GSTR + lc];
            va.x = ftf(va.x); va.y = ftf(va.y); va.z = ftf(va.z); va.w = ftf(va.w);
            *(float4*)&ac[r * GSTR + lc] = va;
            float4 vb = *(float4*)&bc[r * GSTR + lc];
            vb.x = ftf(vb.x); vb.y = ftf(vb.y); vb.z = ftf(vb.z); vb.w = ftf(vb.w);
            *(float4*)&bc[r * GSTR + lc] = vb;
        }

        // issue stage kt+2 (different buffer; safe before the barrier)
        if (kt + 2 < ntiles) {
            const int k0 = (kt + 2) << 5;
            int sn = st + 2; if (sn >= NSTG) sn -= NSTG;
            float* an = As + sn * TILEW;
            float* bn = Bs + sn * TILEW;
#pragma unroll
            for (int i = 0; i < 4; i++) {
                int r = lr + i * 32;
                cpasync16(&an[r * GSTR + lc], &A[(m0 + r) * K + k0 + lc]);
                cpasync16(&bn[r * GSTR + lc], &B[(n0 + r) * K + k0 + lc]);
            }
            cp_commit();
        }
        __syncthreads();   // converted data visible to all warps

        const unsigned* au = (const unsigned*)ac;
        const unsigned* bu = (const unsigned*)bc;
#pragma unroll
        for (int ks = 0; ks < 4; ks++) {
            const int kk = ks * 8;
            unsigned bf[4][2];
#pragma unroll
            for (int nt = 0; nt < 4; nt++) {
                bf[nt][0] = bu[(nw + nt * 8 + g) * GSTR + kk + t];
                bf[nt][1] = bu[(nw + nt * 8 + g) * GSTR + kk + 4 + t];
            }
#pragma unroll
            for (int mt = 0; mt < 4; mt++) {
                unsigned a0 = au[(mw + mt * 16 + g) * GSTR + kk + t];
                unsigned a1 = au[(mw + mt * 16 + 8 + g) * GSTR + kk + t];
                unsigned a2 = au[(mw + mt * 16 + g) * GSTR + kk + 4 + t];
                unsigned a3 = au[(mw + mt * 16 + 8 + g) * GSTR + kk + 4 + t];
#pragma unroll
                for (int nt = 0; nt < 4; nt++) {
                    asm volatile(
                        "mma.sync.aligned.m16n8k8.row.col.f32.tf32.tf32.f32 "
                        "{%0,%1,%2,%3}, {%4,%5,%6,%7}, {%8,%9}, {%0,%1,%2,%3};"
                        : "+f"(acc[mt][nt][0]), "+f"(acc[mt][nt][1]),
                          "+f"(acc[mt][nt][2]), "+f"(acc[mt][nt][3])
                        : "r"(a0), "r"(a1), "r"(a2), "r"(a3),
                          "r"(bf[nt][0]), "r"(bf[nt][1]));
                }
            }
        }
        st++; if (st >= NSTG) st = 0;
    }

    if (mode == 1) {
        // ---- fused RoPE epilogue: stage (acc + bias) to smem, rotate, store
        float* stg = sm;
        __syncthreads();   // pipeline buffers no longer needed
#pragma unroll
        for (int mt = 0; mt < 4; mt++) {
#pragma unroll
            for (int nt = 0; nt < 4; nt++) {
                int row = mw + mt * 16 + g;
                int col = nw + nt * 8 + t * 2;
                float b0 = bias[n0 + col], b1 = bias[n0 + col + 1];
                stg[row * ESTR + col]           = acc[mt][nt][0] + b0;
                stg[row * ESTR + col + 1]       = acc[mt][nt][1] + b1;
                stg[(row + 8) * ESTR + col]     = acc[mt][nt][2] + b0;
                stg[(row + 8) * ESTR + col + 1] = acc[mt][nt][3] + b1;
            }
        }
        __syncthreads();

        for (int i = tid; i < 128 * 64; i += 256) {
            int row = i >> 6;
            int cc  = (i & 63) << 1;
            int d   = cc & 63;
            int s_g = m0 + row;
            if (d < 32) {
                float c0 = rope_g[s_g * HD + d];
                float c1 = rope_g[s_g * HD + d + 1];
                float s0 = rope_g[s_g * HD + 32 + d];
                float s1 = rope_g[s_g * HD + 32 + d + 1];
                float x10 = stg[row * ESTR + cc];
                float x11 = stg[row * ESTR + cc + 1];
                float x20 = stg[row * ESTR + cc + 32];
                float x21 = stg[row * ESTR + cc + 33];
                *(float2*)&C[s_g * N + n0 + cc] =
                    make_float2(ftf(x10 * c0 - x20 * s0),
                                ftf(x11 * c1 - x21 * s1));
            } else {
                int i0 = d - 32;
                float c0 = rope_g[s_g * HD + i0];
                float c1 = rope_g[s_g * HD + i0 + 1];
                float s0 = rope_g[s_g * HD + 32 + i0];
                float s1 = rope_g[s_g * HD + 32 + i0 + 1];
                float x10 = stg[row * ESTR + cc - 32];
                float x11 = stg[row * ESTR + cc - 31];
                float x20 = stg[row * ESTR + cc];
                float x21 = stg[row * ESTR + cc + 1];
                *(float2*)&C[s_g * N + n0 + cc] =
                    make_float2(ftf(x10 * s0 + x20 * c0),
                                ftf(x11 * s1 + x21 * c1));
            }
        }
    } else {
#pragma unroll
        for (int mt = 0; mt < 4; mt++) {
#pragma unroll
            for (int nt = 0; nt < 4; nt++) {
                int row = m0 + mw + mt * 16 + g;
                int col = n0 + nw + nt * 8 + t * 2;
                float b0 = bias[col], b1 = bias[col + 1];
                float v0 = acc[mt][nt][0] + b0, v1 = acc[mt][nt][1] + b1;
                float v2 = acc[mt][nt][2] + b0, v3 = acc[mt][nt][3] + b1;
                if (mode == 2) {
                    v0 = ftf(v0); v1 = ftf(v1); v2 = ftf(v2); v3 = ftf(v3);
                }
                *(float2*)&C[row * N + col]       = make_float2(v0, v1);
                *(float2*)&C[(row + 8) * N + col] = make_float2(v2, v3);
            }
        }
    }
}

#define GEMM_SMEM (2 * NSTG * TILEW * (int)sizeof(float))   // 110592 B

__global__ void __launch_bounds__(256)
qkv_gemm(const float* __restrict__ x, const float* __restrict__ rope_g,
         const float* __restrict__ wq, const float* __restrict__ bq, float* __restrict__ oq,
         const float* __restrict__ wk, const float* __restrict__ bk, float* __restrict__ ok,
         const float* __restrict__ wv, const float* __restrict__ bv, float* __restrict__ ov)
{
    extern __shared__ float sm[];
    const int bx = blockIdx.x;
    const float *B, *bias; float* C; int N, n0, mode;
    if (bx < 16)      { B = wq; bias = bq; C = oq; N = 2048; n0 = bx * 128;        mode = 1; }
    else if (bx < 20) { B = wk; bias = bk; C = ok; N = 512;  n0 = (bx - 16) * 128; mode = 1; }
    else              { B = wv; bias = bv; C = ov; N = 512;  n0 = (bx - 20) * 128; mode = 2; }
    gemm_core(x, B, bias, C, N, DIM, blockIdx.y * 128, n0, sm, mode, rope_g);
}

__global__ void __launch_bounds__(256)
gemm2(const float* __restrict__ A, const float* __restrict__ B,
      const float* __restrict__ bias, float* __restrict__ C, int N, int K)
{
    extern __shared__ float sm[];
    gemm_core(A, B, bias, C, N, K, blockIdx.y * 128, blockIdx.x * 128, sm, 0,
              (const float*)0);
}

// ---------------- Flash attention: CVT-free mma loops (round-10 proven) -----
// BQ=256, BKV=64, 8 warps x 32 q-rows, cp.async double-buffered K/V + Q.
// Q/K rounded by fused rope, V rounded in QKV epilogue -> pure LDS fragments.
// K stride 68 -> QK B-frag bank = 4g+t; V stride 72 -> PV B-frag bank = 8t+g.
#define QSTR 68
#define KSTR 68
#define VST2 72
#define PSTR 68
#define ATT_BQ 256
#define ATT_BK 64

#define ATT_SMEM ((ATT_BQ * QSTR + 2 * ATT_BK * KSTR + 2 * ATT_BK * VST2 \
                   + ATT_BQ * PSTR) * (int)sizeof(unsigned))   // 210944 B

__global__ void __launch_bounds__(256)
attn_mma(const float* __restrict__ Q, const float* __restrict__ K,
         const float* __restrict__ V, const float* __restrict__ sinks,
         float* __restrict__ O)
{
    extern __shared__ unsigned sm_u[];
    unsigned* q_s = sm_u;                          // [256][QSTR] tf32 bits
    float*    k_s = (float*)(q_s + ATT_BQ * QSTR); // [2][64][KSTR]
    float*    v_s = k_s + 2 * ATT_BK * KSTR;       // [2][64][VST2]
    unsigned* p_s = (unsigned*)(v_s + 2 * ATT_BK * VST2); // [256][PSTR]

    const int h    = blockIdx.y;
    const int q0   = (gridDim.x - 1 - blockIdx.x) * ATT_BQ;   // heavy-first
    const int kvh  = h >> 2;                       // h / NREP
    const int tid  = threadIdx.x;
    const int lane = tid & 31;
    const int w    = tid >> 5;
    const int g    = lane >> 2;
    const int t    = lane & 3;
    const int mw   = w * 32;                       // warp's 32 q-rows

    const int ntiles = q0 / ATT_BK + 4;

    // ---- prologue: Q (group 0), then K/V tiles 0,1 (groups 1,2) ----
#pragma unroll
    for (int i = 0; i < 16; i++) {
        int idx = tid + i * 256;
        int row = idx >> 4, c4 = (idx & 15) << 2;
        cpasync16(&q_s[row * QSTR + c4], &Q[(q0 + row) * (NH * HD) + h * HD + c4]);
    }
    cp_commit();
#pragma unroll
    for (int p = 0; p < 2; p++) {
        const int k0 = p * ATT_BK;
        float* kd = k_s + p * ATT_BK * KSTR;
        float* vd = v_s + p * ATT_BK * VST2;
#pragma unroll
        for (int i = 0; i < 4; i++) {
            int idx = tid + i * 256;
            int row = idx >> 4, c4 = (idx & 15) << 2;
            cpasync16(&kd[row * KSTR + c4], &K[(k0 + row) * (NKV * HD) + kvh * HD + c4]);
            cpasync16(&vd[row * VST2 + c4], &V[(k0 + row) * (NKV * HD) + kvh * HD + c4]);
        }
        cp_commit();
    }

    float o[2][8][4];
#pragma unroll
    for (int mt = 0; mt < 2; mt++)
#pragma unroll
        for (int nt = 0; nt < 8; nt++)
#pragma unroll
            for (int r = 0; r < 4; r++) o[mt][nt][r] = 0.f;
    float m_st[2][2], l_st[2][2];
#pragma unroll
    for (int mt = 0; mt < 2; mt++) {
        m_st[mt][0] = -INFINITY; m_st[mt][1] = -INFINITY;
        l_st[mt][0] = 0.f;       l_st[mt][1] = 0.f;
    }

    for (int kt = 0; kt < ntiles; kt++) {
        const int k0 = kt * ATT_BK;
        if (kt + 1 < ntiles) cp_wait1(); else cp_wait0();
        __syncthreads();

        const unsigned* kc = (const unsigned*)(k_s + (kt & 1) * ATT_BK * KSTR);
        const unsigned* vc = (const unsigned*)(v_s + (kt & 1) * ATT_BK * VST2);

        const bool active = (k0 <= q0 + mw + 31);
        if (active) {
            // ---- S = Q @ K^T ----
            float s[2][8][4];
#pragma unroll
            for (int mt = 0; mt < 2; mt++)
#pragma unroll
                for (int nt = 0; nt < 8; nt++)
#pragma unroll
                    for (int r = 0; r < 4; r++) s[mt][nt][r] = 0.f;

#pragma unroll
            for (int ks = 0; ks < 8; ks++) {
                const int kk = ks * 8;
                unsigned a[2][4];
#pragma unroll
                for (int mt = 0; mt < 2; mt++) {
                    const int rb = (mw + mt * 16 + g) * QSTR;
                    a[mt][0] = q_s[rb + kk + t];
                    a[mt][1] = q_s[rb + 8 * QSTR + kk + t];
                    a[mt][2] = q_s[rb + kk + 4 + t];
                    a[mt][3] = q_s[rb + 8 * QSTR + kk + 4 + t];
                }
#pragma unroll
                for (int nt = 0; nt < 8; nt++) {
                    unsigned b0 = kc[(nt * 8 + g) * KSTR + kk + t];
                    unsigned b1 = kc[(nt * 8 + g) * KSTR + kk + 4 + t];
#pragma unroll
                    for (int mt = 0; mt < 2; mt++) {
                        asm volatile(
                            "mma.sync.aligned.m16n8k8.row.col.f32.tf32.tf32.f32 "
                            "{%0,%1,%2,%3}, {%4,%5,%6,%7}, {%8,%9}, {%0,%1,%2,%3};"
                            : "+f"(s[mt][nt][0]), "+f"(s[mt][nt][1]),
                              "+f"(s[mt][nt][2]), "+f"(s[mt][nt][3])
                            : "r"(a[mt][0]), "r"(a[mt][1]), "r"(a[mt][2]), "r"(a[mt][3]),
                              "r"(b0), "r"(b1));
                    }
                }
            }

            // ---- scale + causal mask (near-diagonal only) ----
            if (k0 + ATT_BK - 1 > q0 + mw) {
#pragma unroll
                for (int mt = 0; mt < 2; mt++) {
                    int qa = q0 + mw + mt * 16 + g;
                    int qb = qa + 8;
#pragma unroll
                    for (int nt = 0; nt < 8; nt++) {
                        int kg0 = k0 + nt * 8 + 2 * t;
                        s[mt][nt][0] = (kg0     <= qa) ? s[mt][nt][0] * ATT_SCALE : -1e30f;
                        s[mt][nt][1] = (kg0 + 1 <= qa) ? s[mt][nt][1] * ATT_SCALE : -1e30f;
                        s[mt][nt][2] = (kg0     <= qb) ? s[mt][nt][2] * ATT_SCALE : -1e30f;
                        s[mt][nt][3] = (kg0 + 1 <= qb) ? s[mt][nt][3] * ATT_SCALE : -1e30f;
                    }
                }
            } else {
#pragma unroll
                for (int mt = 0; mt < 2; mt++)
#pragma unroll
                    for (int nt = 0; nt < 8; nt++)
#pragma unroll
                        for (int r = 0; r < 4; r++) s[mt][nt][r] *= ATT_SCALE;
            }

            // ---- online softmax ----
#pragma unroll
            for (int mt = 0; mt < 2; mt++) {
                float mlA = -INFINITY, mlB = -INFINITY;
#pragma unroll
                for (int nt = 0; nt < 8; nt++) {
                    mlA = fmaxf(mlA, fmaxf(s[mt][nt][0], s[mt][nt][1]));
                    mlB = fmaxf(mlB, fmaxf(s[mt][nt][2], s[mt][nt][3]));
                }
                mlA = fmaxf(mlA, __shfl_xor_sync(0xffffffffu, mlA, 1));
                mlA = fmaxf(mlA, __shfl_xor_sync(0xffffffffu, mlA, 2));
                mlB = fmaxf(mlB, __shfl_xor_sync(0xffffffffu, mlB, 1));
                mlB = fmaxf(mlB, __shfl_xor_sync(0xffffffffu, mlB, 2));

                float mnA = fmaxf(m_st[mt][0], mlA);
                float mnB = fmaxf(m_st[mt][1], mlB);
                float alA = __expf(m_st[mt][0] - mnA);
                float alB = __expf(m_st[mt][1] - mnB);

                float sumA = 0.f, sumB = 0.f;
                const int rbA = (mw + mt * 16 + g) * PSTR;
                const int rbB = rbA + 8 * PSTR;
#pragma unroll
                for (int nt = 0; nt < 8; nt++) {
                    float p0 = __expf(s[mt][nt][0] - mnA);
                    float p1 = __expf(s[mt][nt][1] - mnA);
                    float p2 = __expf(s[mt][nt][2] - mnB);
                    float p3 = __expf(s[mt][nt][3] - mnB);
                    sumA += p0 + p1;
                    sumB += p2 + p3;
                    int col = nt * 8 + 2 * t;
                    *(uint2*)&p_s[rbA + col] = make_uint2(f2tf(p0), f2tf(p1));
                    *(uint2*)&p_s[rbB + col] = make_uint2(f2tf(p2), f2tf(p3));
                }
                sumA += __shfl_xor_sync(0xffffffffu, sumA, 1);
                sumA += __shfl_xor_sync(0xffffffffu, sumA, 2);
                sumB += __shfl_xor_sync(0xffffffffu, sumB, 1);
                sumB += __shfl_xor_sync(0xffffffffu, sumB, 2);

                l_st[mt][0] = l_st[mt][0] * alA + sumA;  m_st[mt][0] = mnA;
                l_st[mt][1] = l_st[mt][1] * alB + sumB;  m_st[mt][1] = mnB;

#pragma unroll
                for (int nt = 0; nt < 8; nt++) {
                    o[mt][nt][0] *= alA; o[mt][nt][1] *= alA;
                    o[mt][nt][2] *= alB; o[mt][nt][3] *= alB;
                }
            }

            __syncwarp();   // p_s rows private to this warp

            // ---- O += P @ V ----
#pragma unroll
            for (int ks = 0; ks < 8; ks++) {
                const int kk = ks * 8;
                unsigned a[2][4];
#pragma unroll
                for (int mt = 0; mt < 2; mt++) {
                    const int rb = (mw + mt * 16 + g) * PSTR;
                    a[mt][0] = p_s[rb + kk + t];
                    a[mt][1] = p_s[rb + 8 * PSTR + kk + t];
                    a[mt][2] = p_s[rb + kk + 4 + t];
                    a[mt][3] = p_s[rb + 8 * PSTR + kk + 4 + t];
                }
#pragma unroll
                for (int nt = 0; nt < 8; nt++) {
                    unsigned b0 = vc[(kk + t) * VST2 + nt * 8 + g];
                    unsigned b1 = vc[(kk + 4 + t) * VST2 + nt * 8 + g];
#pragma unroll
                    for (int mt = 0; mt < 2; mt++) {
                        asm volatile(
                            "mma.sync.aligned.m16n8k8.row.col.f32.tf32.tf32.f32 "
                            "{%0,%1,%2,%3}, {%4,%5,%6,%7}, {%8,%9}, {%0,%1,%2,%3};"
                            : "+f"(o[mt][nt][0]), "+f"(o[mt][nt][1]),
                              "+f"(o[mt][nt][2]), "+f"(o[mt][nt][3])
                            : "r"(a[mt][0]), "r"(a[mt][1]), "r"(a[mt][2]), "r"(a[mt][3]),
                              "r"(b0), "r"(b1));
                    }
                }
            }
        }
        __syncthreads();

        // issue K/V tile kt+2 into the buffer just released
        if (kt + 2 < ntiles) {
            const int kn = (kt + 2) * ATT_BK;
            float* kd = k_s + (kt & 1) * ATT_BK * KSTR;
            float* vd = v_s + (kt & 1) * ATT_BK * VST2;
#pragma unroll
            for (int i = 0; i < 4; i++) {
                int idx = tid + i * 256;
                int row = idx >> 4, c4 = (idx & 15) << 2;
                cpasync16(&kd[row * KSTR + c4], &K[(kn + row) * (NKV * HD) + kvh * HD + c4]);
                cpasync16(&vd[row * VST2 + c4], &V[(kn + row) * (NKV * HD) + kvh * HD + c4]);
            }
            cp_commit();
        }
    }

    // ---- epilogue: normalize + sink scale ----
    float snk = sinks[h];
#pragma unroll
    for (int mt = 0; mt < 2; mt++) {
        int qa = q0 + mw + mt * 16 + g;
        int qb = qa + 8;
        float lseA = m_st[mt][0] + logf(l_st[mt][0]);
        float lseB = m_st[mt][1] + logf(l_st[mt][1]);
        float invA = (1.f / (1.f + __expf(-(lseA - snk)))) / l_st[mt][0];
        float invB = (1.f / (1.f + __expf(-(lseB - snk)))) / l_st[mt][1];
#pragma unroll
        for (int nt = 0; nt < 8; nt++) {
            int col = nt * 8 + 2 * t;
            *(float2*)&O[qa * (NH * HD) + h * HD + col] =
                make_float2(o[mt][nt][0] * invA, o[mt][nt][1] * invA);
            *(float2*)&O[qb * (NH * HD) + h * HD + col] =
                make_float2(o[mt][nt][2] * invB, o[mt][nt][3] * invB);
        }
    }
}

// ---------------- launch ----------------------------------------------------
extern "C" void kernel_launch(void* const* d_in, const int* in_sizes, int n_in,
                              void* d_out, int out_size)
{
    const float* x     = (const float*)d_in[0];
    const float* rope  = (const float*)d_in[1];
    const float* wq_w  = (const float*)d_in[2];
    const float* wq_b  = (const float*)d_in[3];
    const float* wk_w  = (const float*)d_in[4];
    const float* wk_b  = (const float*)d_in[5];
    const float* wv_w  = (const float*)d_in[6];
    const float* wv_b  = (const float*)d_in[7];
    const float* wo_w  = (const float*)d_in[8];
    const float* wo_b  = (const float*)d_in[9];
    const float* sinks = (const float*)d_in[10];
    float* out = (float*)d_out;

    float *gq, *gk, *gv, *ga;
    cudaGetSymbolAddress((void**)&gq, g_q);
    cudaGetSymbolAddress((void**)&gk, g_k);
    cudaGetSymbolAddress((void**)&gv, g_v);
    cudaGetSymbolAddress((void**)&ga, g_attn);

    cudaFuncSetAttribute(qkv_gemm, cudaFuncAttributeMaxDynamicSharedMemorySize,
                         GEMM_SMEM);
    cudaFuncSetAttribute(gemm2, cudaFuncAttributeMaxDynamicSharedMemorySize,
                         GEMM_SMEM);
    cudaFuncSetAttribute(attn_mma, cudaFuncAttributeMaxDynamicSharedMemorySize,
                         ATT_SMEM);

    // Fused QKV projections + RoPE (Q,K) + tf32 rounding (Q,K,V)
    qkv_gemm<<<dim3(24, 16), 256, GEMM_SMEM>>>(x, rope,
                                               wq_w, wq_b, gq,
                                               wk_w, wk_b, gk,
                                               wv_w, wv_b, gv);

    // Flash attention (CVT-free mma loops, heavy-first)
    attn_mma<<<dim3(S_LEN / ATT_BQ, NH), 256, ATT_SMEM>>>(gq, gk, gv, sinks, ga);

    // Output projection
    gemm2<<<dim3(16, 16), 256, GEMM_SMEM>>>(ga, wo_w, wo_b, out, DIM, NH * HD);
}

// round 14
// speedup vs baseline: 1.0542x; 1.0542x over previous
#include <cuda_runtime.h>
#include <math.h>

#define S_LEN 2048
#define DIM   2048
#define NH    32
#define NKV   8
#define HD    64
#define NREP  4           // NH / NKV
#define QSCALE 0.18033688f   // ATT_SCALE * log2(e) = 0.125 * 1.44269504
#define LN2    0.69314718f

// ---------------- scratch (device globals; no allocation allowed) ----------
__device__ float g_q[S_LEN * NH * HD];     // 16 MB
__device__ float g_k[S_LEN * NKV * HD];    // 4 MB
__device__ float g_v[S_LEN * NKV * HD];    // 4 MB
__device__ float g_attn[S_LEN * NH * HD];  // 16 MB

__device__ __forceinline__ unsigned f2tf(float f) {
    unsigned r;
    asm("cvt.rna.tf32.f32 %0, %1;" : "=r"(r) : "f"(f));
    return r;
}
__device__ __forceinline__ float ftf(float f) {
    return __uint_as_float(f2tf(f));
}

__device__ __forceinline__ void cpasync16(void* smem_ptr, const void* gptr) {
    unsigned s = (unsigned)__cvta_generic_to_shared(smem_ptr);
    asm volatile("cp.async.cg.shared.global [%0], [%1], 16;\n" :: "r"(s), "l"(gptr));
}
__device__ __forceinline__ void cp_commit() {
    asm volatile("cp.async.commit_group;\n");
}
__device__ __forceinline__ void cp_wait0() {
    asm volatile("cp.async.wait_group 0;\n");
}
__device__ __forceinline__ void cp_wait1() {
    asm volatile("cp.async.wait_group 1;\n");
}

// ---------------- TF32 tensor-core GEMM (round-12 proven config) ------------
// C[M,N] = A[M,K] @ B[N,K]^T + bias[N]
// 128x128 block tile, BK=32, 3-stage cp.async, 8 warps (2x4), warp tile 64x32.
// Epilogue modes: 0 = plain, 1 = fused RoPE (scaled, tf32-rounded),
//                 2 = tf32-rounded.
#define GSTR  36
#define TILEW (128 * GSTR)
#define NSTG  3
#define ESTR  132   // epilogue staging stride

__device__ __forceinline__ void gemm_core(
    const float* __restrict__ A, const float* __restrict__ B,
    const float* __restrict__ bias, float* __restrict__ C,
    int N, int K, int m0, int n0, float* sm, int mode,
    const float* __restrict__ rope_g, float oscale)
{
    float* As = sm;
    float* Bs = sm + NSTG * TILEW;

    const int tid  = threadIdx.x;
    const int lane = tid & 31;
    const int w    = tid >> 5;
    const int mw   = (w >> 2) * 64;
    const int nw   = (w & 3) * 32;
    const int g    = lane >> 2;
    const int t    = lane & 3;

    const int lr = tid >> 3;
    const int lc = (tid & 7) << 2;

    float acc[4][4][4];
#pragma unroll
    for (int mt = 0; mt < 4; mt++)
#pragma unroll
        for (int nt = 0; nt < 4; nt++)
#pragma unroll
            for (int r = 0; r < 4; r++) acc[mt][nt][r] = 0.f;

    const int ntiles = K >> 5;

#pragma unroll
    for (int p = 0; p < 2; p++) {
        float* ad = As + p * TILEW;
        float* bd = Bs + p * TILEW;
        const int k0 = p << 5;
#pragma unroll
        for (int i = 0; i < 4; i++) {
            int r = lr + i * 32;
            cpasync16(&ad[r * GSTR + lc], &A[(m0 + r) * K + k0 + lc]);
            cpasync16(&bd[r * GSTR + lc], &B[(n0 + r) * K + k0 + lc]);
        }
        cp_commit();
    }

    int st = 0;
    for (int kt = 0; kt < ntiles; kt++) {
        if (kt + 1 < ntiles) cp_wait1(); else cp_wait0();
        __syncthreads();

        if (kt + 2 < ntiles) {
            const int k0 = (kt + 2) << 5;
            int sn = st + 2; if (sn >= NSTG) sn -= NSTG;
            float* an = As + sn * TILEW;
            float* bn = Bs + sn * TILEW;
#pragma unroll
            for (int i = 0; i < 4; i++) {
                int r = lr + i * 32;
                cpasync16(&an[r * GSTR + lc], &A[(m0 + r) * K + k0 + lc]);
                cpasync16(&bn[r * GSTR + lc], &B[(n0 + r) * K + k0 + lc]);
            }
            cp_commit();
        }

        const float* ac = As + st * TILEW;
        const float* bc = Bs + st * TILEW;
#pragma unroll
        for (int ks = 0; ks < 4; ks++) {
            const int kk = ks * 8;
            unsigned bf[4][2];
#pragma unroll
            for (int nt = 0; nt < 4; nt++) {
                bf[nt][0] = f2tf(bc[(nw + nt * 8 + g) * GSTR + kk + t]);
                bf[nt][1] = f2tf(bc[(nw + nt * 8 + g) * GSTR + kk + 4 + t]);
            }
#pragma unroll
            for (int mt = 0; mt < 4; mt++) {
                unsigned a0 = f2tf(ac[(mw + mt * 16 + g) * GSTR + kk + t]);
                unsigned a1 = f2tf(ac[(mw + mt * 16 + 8 + g) * GSTR + kk + t]);
                unsigned a2 = f2tf(ac[(mw + mt * 16 + g) * GSTR + kk + 4 + t]);
                unsigned a3 = f2tf(ac[(mw + mt * 16 + 8 + g) * GSTR + kk + 4 + t]);
#pragma unroll
                for (int nt = 0; nt < 4; nt++) {
                    asm volatile(
                        "mma.sync.aligned.m16n8k8.row.col.f32.tf32.tf32.f32 "
                        "{%0,%1,%2,%3}, {%4,%5,%6,%7}, {%8,%9}, {%0,%1,%2,%3};"
                        : "+f"(acc[mt][nt][0]), "+f"(acc[mt][nt][1]),
                          "+f"(acc[mt][nt][2]), "+f"(acc[mt][nt][3])
                        : "r"(a0), "r"(a1), "r"(a2), "r"(a3),
                          "r"(bf[nt][0]), "r"(bf[nt][1]));
                }
            }
        }
        st++; if (st >= NSTG) st = 0;
    }

    if (mode == 1) {
        // ---- fused RoPE epilogue: stage (acc + bias), rotate, scale, store
        float* stg = sm;
        __syncthreads();
#pragma unroll
        for (int mt = 0; mt < 4; mt++) {
#pragma unroll
            for (int nt = 0; nt < 4; nt++) {
                int row = mw + mt * 16 + g;
                int col = nw + nt * 8 + t * 2;
                float b0 = bias[n0 + col], b1 = bias[n0 + col + 1];
                stg[row * ESTR + col]           = acc[mt][nt][0] + b0;
                stg[row * ESTR + col + 1]       = acc[mt][nt][1] + b1;
                stg[(row + 8) * ESTR + col]     = acc[mt][nt][2] + b0;
                stg[(row + 8) * ESTR + col + 1] = acc[mt][nt][3] + b1;
            }
        }
        __syncthreads();

        for (int i = tid; i < 128 * 64; i += 256) {
            int row = i >> 6;
            int cc  = (i & 63) << 1;
            int d   = cc & 63;
            int s_g = m0 + row;
            if (d < 32) {
                float c0 = rope_g[s_g * HD + d];
                float c1 = rope_g[s_g * HD + d + 1];
                float s0 = rope_g[s_g * HD + 32 + d];
                float s1 = rope_g[s_g * HD + 32 + d + 1];
                float x10 = stg[row * ESTR + cc];
                float x11 = stg[row * ESTR + cc + 1];
                float x20 = stg[row * ESTR + cc + 32];
                float x21 = stg[row * ESTR + cc + 33];
                *(float2*)&C[s_g * N + n0 + cc] =
                    make_float2(ftf((x10 * c0 - x20 * s0) * oscale),
                                ftf((x11 * c1 - x21 * s1) * oscale));
            } else {
                int i0 = d - 32;
                float c0 = rope_g[s_g * HD + i0];
                float c1 = rope_g[s_g * HD + i0 + 1];
                float s0 = rope_g[s_g * HD + 32 + i0];
                float s1 = rope_g[s_g * HD + 32 + i0 + 1];
                float x10 = stg[row * ESTR + cc - 32];
                float x11 = stg[row * ESTR + cc - 31];
                float x20 = stg[row * ESTR + cc];
                float x21 = stg[row * ESTR + cc + 1];
                *(float2*)&C[s_g * N + n0 + cc] =
                    make_float2(ftf((x10 * s0 + x20 * c0) * oscale),
                                ftf((x11 * s1 + x21 * c1) * oscale));
            }
        }
    } else {
#pragma unroll
        for (int mt = 0; mt < 4; mt++) {
#pragma unroll
            for (int nt = 0; nt < 4; nt++) {
                int row = m0 + mw + mt * 16 + g;
                int col = n0 + nw + nt * 8 + t * 2;
                float b0 = bias[col], b1 = bias[col + 1];
                float v0 = acc[mt][nt][0] + b0, v1 = acc[mt][nt][1] + b1;
                float v2 = acc[mt][nt][2] + b0, v3 = acc[mt][nt][3] + b1;
                if (mode == 2) {
                    v0 = ftf(v0); v1 = ftf(v1); v2 = ftf(v2); v3 = ftf(v3);
                }
                *(float2*)&C[row * N + col]       = make_float2(v0, v1);
                *(float2*)&C[(row + 8) * N + col] = make_float2(v2, v3);
            }
        }
    }
}

#define GEMM_SMEM (2 * NSTG * TILEW * (int)sizeof(float))   // 110592 B

__global__ void __launch_bounds__(256)
qkv_gemm(const float* __restrict__ x, const float* __restrict__ rope_g,
         const float* __restrict__ wq, const float* __restrict__ bq, float* __restrict__ oq,
         const float* __restrict__ wk, const float* __restrict__ bk, float* __restrict__ ok,
         const float* __restrict__ wv, const float* __restrict__ bv, float* __restrict__ ov)
{
    extern __shared__ float sm[];
    const int bx = blockIdx.x;
    const float *B, *bias; float* C; int N, n0, mode; float osc;
    if (bx < 16)      { B = wq; bias = bq; C = oq; N = 2048; n0 = bx * 128;
                        mode = 1; osc = QSCALE; }   // Q pre-scaled for exp2 softmax
    else if (bx < 20) { B = wk; bias = bk; C = ok; N = 512;  n0 = (bx - 16) * 128;
                        mode = 1; osc = 1.0f; }
    else              { B = wv; bias = bv; C = ov; N = 512;  n0 = (bx - 20) * 128;
                        mode = 2; osc = 1.0f; }
    gemm_core(x, B, bias, C, N, DIM, blockIdx.y * 128, n0, sm, mode, rope_g, osc);
}

__global__ void __launch_bounds__(256)
gemm2(const float* __restrict__ A, const float* __restrict__ B,
      const float* __restrict__ bias, float* __restrict__ C, int N, int K)
{
    extern __shared__ float sm[];
    gemm_core(A, B, bias, C, N, K, blockIdx.y * 128, blockIdx.x * 128, sm, 0,
              (const float*)0, 1.0f);
}

// ---------------- Flash attention: exp2 softmax, CVT-free mma ---------------
// BQ=256, BKV=64, 8 warps x 32 q-rows, cp.async double-buffered K/V + Q.
// Q pre-scaled by ATT_SCALE*log2(e) -> scores are log2-domain; no scale pass,
// softmax is bare exp2f. K stride 68 -> QK B-frag bank = 4g+t;
// V stride 72 -> PV B-frag bank = 8t+g.
#define QSTR 68
#define KSTR 68
#define VST2 72
#define PSTR 68
#define ATT_BQ 256
#define ATT_BK 64

#define ATT_SMEM ((ATT_BQ * QSTR + 2 * ATT_BK * KSTR + 2 * ATT_BK * VST2 \
                   + ATT_BQ * PSTR) * (int)sizeof(unsigned))   // 210944 B

__global__ void __launch_bounds__(256)
attn_mma(const float* __restrict__ Q, const float* __restrict__ K,
         const float* __restrict__ V, const float* __restrict__ sinks,
         float* __restrict__ O)
{
    extern __shared__ unsigned sm_u[];
    unsigned* q_s = sm_u;                          // [256][QSTR] tf32 bits
    float*    k_s = (float*)(q_s + ATT_BQ * QSTR); // [2][64][KSTR]
    float*    v_s = k_s + 2 * ATT_BK * KSTR;       // [2][64][VST2]
    unsigned* p_s = (unsigned*)(v_s + 2 * ATT_BK * VST2); // [256][PSTR]

    const int h    = blockIdx.y;
    const int q0   = (gridDim.x - 1 - blockIdx.x) * ATT_BQ;   // heavy-first
    const int kvh  = h >> 2;                       // h / NREP
    const int tid  = threadIdx.x;
    const int lane = tid & 31;
    const int w    = tid >> 5;
    const int g    = lane >> 2;
    const int t    = lane & 3;
    const int mw   = w * 32;                       // warp's 32 q-rows

    const int ntiles = q0 / ATT_BK + 4;

    // ---- prologue: Q (group 0), then K/V tiles 0,1 (groups 1,2) ----
#pragma unroll
    for (int i = 0; i < 16; i++) {
        int idx = tid + i * 256;
        int row = idx >> 4, c4 = (idx & 15) << 2;
        cpasync16(&q_s[row * QSTR + c4], &Q[(q0 + row) * (NH * HD) + h * HD + c4]);
    }
    cp_commit();
#pragma unroll
    for (int p = 0; p < 2; p++) {
        const int k0 = p * ATT_BK;
        float* kd = k_s + p * ATT_BK * KSTR;
        float* vd = v_s + p * ATT_BK * VST2;
#pragma unroll
        for (int i = 0; i < 4; i++) {
            int idx = tid + i * 256;
            int row = idx >> 4, c4 = (idx & 15) << 2;
            cpasync16(&kd[row * KSTR + c4], &K[(k0 + row) * (NKV * HD) + kvh * HD + c4]);
            cpasync16(&vd[row * VST2 + c4], &V[(k0 + row) * (NKV * HD) + kvh * HD + c4]);
        }
        cp_commit();
    }

    float o[2][8][4];
#pragma unroll
    for (int mt = 0; mt < 2; mt++)
#pragma unroll
        for (int nt = 0; nt < 8; nt++)
#pragma unroll
            for (int r = 0; r < 4; r++) o[mt][nt][r] = 0.f;
    float m_st[2][2], l_st[2][2];
#pragma unroll
    for (int mt = 0; mt < 2; mt++) {
        m_st[mt][0] = -INFINITY; m_st[mt][1] = -INFINITY;
        l_st[mt][0] = 0.f;       l_st[mt][1] = 0.f;
    }

    for (int kt = 0; kt < ntiles; kt++) {
        const int k0 = kt * ATT_BK;
        if (kt + 1 < ntiles) cp_wait1(); else cp_wait0();
        __syncthreads();

        const unsigned* kc = (const unsigned*)(k_s + (kt & 1) * ATT_BK * KSTR);
        const unsigned* vc = (const unsigned*)(v_s + (kt & 1) * ATT_BK * VST2);

        const bool active = (k0 <= q0 + mw + 31);
        if (active) {
            // ---- S = Q @ K^T (scores already in log2 domain) ----
            float s[2][8][4];
#pragma unroll
            for (int mt = 0; mt < 2; mt++)
#pragma unroll
                for (int nt = 0; nt < 8; nt++)
#pragma unroll
                    for (int r = 0; r < 4; r++) s[mt][nt][r] = 0.f;

#pragma unroll
            for (int ks = 0; ks < 8; ks++) {
                const int kk = ks * 8;
                unsigned a[2][4];
#pragma unroll
                for (int mt = 0; mt < 2; mt++) {
                    const int rb = (mw + mt * 16 + g) * QSTR;
                    a[mt][0] = q_s[rb + kk + t];
                    a[mt][1] = q_s[rb + 8 * QSTR + kk + t];
                    a[mt][2] = q_s[rb + kk + 4 + t];
                    a[mt][3] = q_s[rb + 8 * QSTR + kk + 4 + t];
                }
#pragma unroll
                for (int nt = 0; nt < 8; nt++) {
                    unsigned b0 = kc[(nt * 8 + g) * KSTR + kk + t];
                    unsigned b1 = kc[(nt * 8 + g) * KSTR + kk + 4 + t];
#pragma unroll
                    for (int mt = 0; mt < 2; mt++) {
                        asm volatile(
                            "mma.sync.aligned.m16n8k8.row.col.f32.tf32.tf32.f32 "
                            "{%0,%1,%2,%3}, {%4,%5,%6,%7}, {%8,%9}, {%0,%1,%2,%3};"
                            : "+f"(s[mt][nt][0]), "+f"(s[mt][nt][1]),
                              "+f"(s[mt][nt][2]), "+f"(s[mt][nt][3])
                            : "r"(a[mt][0]), "r"(a[mt][1]), "r"(a[mt][2]), "r"(a[mt][3]),
                              "r"(b0), "r"(b1));
                    }
                }
            }

            // ---- causal mask (diagonal-region tiles only; no scale pass) ----
            if (k0 + ATT_BK - 1 > q0 + mw) {
#pragma unroll
                for (int mt = 0; mt < 2; mt++) {
                    int qa = q0 + mw + mt * 16 + g;
                    int qb = qa + 8;
#pragma unroll
                    for (int nt = 0; nt < 8; nt++) {
                        int kg0 = k0 + nt * 8 + 2 * t;
                        if (kg0     > qa) s[mt][nt][0] = -1e30f;
                        if (kg0 + 1 > qa) s[mt][nt][1] = -1e30f;
                        if (kg0     > qb) s[mt][nt][2] = -1e30f;
                        if (kg0 + 1 > qb) s[mt][nt][3] = -1e30f;
                    }
                }
            }

            // ---- online softmax (base 2) ----
#pragma unroll
            for (int mt = 0; mt < 2; mt++) {
                float mlA = -INFINITY, mlB = -INFINITY;
#pragma unroll
                for (int nt = 0; nt < 8; nt++) {
                    mlA = fmaxf(mlA, fmaxf(s[mt][nt][0], s[mt][nt][1]));
                    mlB = fmaxf(mlB, fmaxf(s[mt][nt][2], s[mt][nt][3]));
                }
                mlA = fmaxf(mlA, __shfl_xor_sync(0xffffffffu, mlA, 1));
                mlA = fmaxf(mlA, __shfl_xor_sync(0xffffffffu, mlA, 2));
                mlB = fmaxf(mlB, __shfl_xor_sync(0xffffffffu, mlB, 1));
                mlB = fmaxf(mlB, __shfl_xor_sync(0xffffffffu, mlB, 2));

                float mnA = fmaxf(m_st[mt][0], mlA);
                float mnB = fmaxf(m_st[mt][1], mlB);
                float alA = exp2f(m_st[mt][0] - mnA);
                float alB = exp2f(m_st[mt][1] - mnB);

                float sumA = 0.f, sumB = 0.f;
                const int rbA = (mw + mt * 16 + g) * PSTR;
                const int rbB = rbA + 8 * PSTR;
#pragma unroll
                for (int nt = 0; nt < 8; nt++) {
                    float p0 = exp2f(s[mt][nt][0] - mnA);
                    float p1 = exp2f(s[mt][nt][1] - mnA);
                    float p2 = exp2f(s[mt][nt][2] - mnB);
                    float p3 = exp2f(s[mt][nt][3] - mnB);
                    sumA += p0 + p1;
                    sumB += p2 + p3;
                    int col = nt * 8 + 2 * t;
                    *(uint2*)&p_s[rbA + col] = make_uint2(f2tf(p0), f2tf(p1));
                    *(uint2*)&p_s[rbB + col] = make_uint2(f2tf(p2), f2tf(p3));
                }
                sumA += __shfl_xor_sync(0xffffffffu, sumA, 1);
                sumA += __shfl_xor_sync(0xffffffffu, sumA, 2);
                sumB += __shfl_xor_sync(0xffffffffu, sumB, 1);
                sumB += __shfl_xor_sync(0xffffffffu, sumB, 2);

                l_st[mt][0] = l_st[mt][0] * alA + sumA;  m_st[mt][0] = mnA;
                l_st[mt][1] = l_st[mt][1] * alB + sumB;  m_st[mt][1] = mnB;

#pragma unroll
                for (int nt = 0; nt < 8; nt++) {
                    o[mt][nt][0] *= alA; o[mt][nt][1] *= alA;
                    o[mt][nt][2] *= alB; o[mt][nt][3] *= alB;
                }
            }

            __syncwarp();   // p_s rows private to this warp

            // ---- O += P @ V ----
#pragma unroll
            for (int ks = 0; ks < 8; ks++) {
                const int kk = ks * 8;
                unsigned a[2][4];
#pragma unroll
                for (int mt = 0; mt < 2; mt++) {
                    const int rb = (mw + mt * 16 + g) * PSTR;
                    a[mt][0] = p_s[rb + kk + t];
                    a[mt][1] = p_s[rb + 8 * PSTR + kk + t];
                    a[mt][2] = p_s[rb + kk + 4 + t];
                    a[mt][3] = p_s[rb + 8 * PSTR + kk + 4 + t];
                }
#pragma unroll
                for (int nt = 0; nt < 8; nt++) {
                    unsigned b0 = vc[(kk + t) * VST2 + nt * 8 + g];
                    unsigned b1 = vc[(kk + 4 + t) * VST2 + nt * 8 + g];
#pragma unroll
                    for (int mt = 0; mt < 2; mt++) {
                        asm volatile(
                            "mma.sync.aligned.m16n8k8.row.col.f32.tf32.tf32.f32 "
                            "{%0,%1,%2,%3}, {%4,%5,%6,%7}, {%8,%9}, {%0,%1,%2,%3};"
                            : "+f"(o[mt][nt][0]), "+f"(o[mt][nt][1]),
                              "+f"(o[mt][nt][2]), "+f"(o[mt][nt][3])
                            : "r"(a[mt][0]), "r"(a[mt][1]), "r"(a[mt][2]), "r"(a[mt][3]),
                              "r"(b0), "r"(b1));
                    }
                }
            }
        }
        __syncthreads();

        // issue K/V tile kt+2 into the buffer just released
        if (kt + 2 < ntiles) {
            const int kn = (kt + 2) * ATT_BK;
            float* kd = k_s + (kt & 1) * ATT_BK * KSTR;
            float* vd = v_s + (kt & 1) * ATT_BK * VST2;
#pragma unroll
            for (int i = 0; i < 4; i++) {
                int idx = tid + i * 256;
                int row = idx >> 4, c4 = (idx & 15) << 2;
                cpasync16(&kd[row * KSTR + c4], &K[(kn + row) * (NKV * HD) + kvh * HD + c4]);
                cpasync16(&vd[row * VST2 + c4], &V[(kn + row) * (NKV * HD) + kvh * HD + c4]);
            }
            cp_commit();
        }
    }

    // ---- epilogue: normalize + sink scale (convert log2 -> natural) ----
    float snk = sinks[h];
#pragma unroll
    for (int mt = 0; mt < 2; mt++) {
        int qa = q0 + mw + mt * 16 + g;
        int qb = qa + 8;
        float lseA = (m_st[mt][0] + __log2f(l_st[mt][0])) * LN2;
        float lseB = (m_st[mt][1] + __log2f(l_st[mt][1])) * LN2;
        float invA = (1.f / (1.f + __expf(-(lseA - snk)))) / l_st[mt][0];
        float invB = (1.f / (1.f + __expf(-(lseB - snk)))) / l_st[mt][1];
#pragma unroll
        for (int nt = 0; nt < 8; nt++) {
            int col = nt * 8 + 2 * t;
            *(float2*)&O[qa * (NH * HD) + h * HD + col] =
                make_float2(o[mt][nt][0] * invA, o[mt][nt][1] * invA);
            *(float2*)&O[qb * (NH * HD) + h * HD + col] =
                make_float2(o[mt][nt][2] * invB, o[mt][nt][3] * invB);
        }
    }
}

// ---------------- launch ----------------------------------------------------
extern "C" void kernel_launch(void* const* d_in, const int* in_sizes, int n_in,
                              void* d_out, int out_size)
{
    const float* x     = (const float*)d_in[0];
    const float* rope  = (const float*)d_in[1];
    const float* wq_w  = (const float*)d_in[2];
    const float* wq_b  = (const float*)d_in[3];
    const float* wk_w  = (const float*)d_in[4];
    const float* wk_b  = (const float*)d_in[5];
    const float* wv_w  = (const float*)d_in[6];
    const float* wv_b  = (const float*)d_in[7];
    const float* wo_w  = (const float*)d_in[8];
    const float* wo_b  = (const float*)d_in[9];
    const float* sinks = (const float*)d_in[10];
    float* out = (float*)d_out;

    float *gq, *gk, *gv, *ga;
    cudaGetSymbolAddress((void**)&gq, g_q);
    cudaGetSymbolAddress((void**)&gk, g_k);
    cudaGetSymbolAddress((void**)&gv, g_v);
    cudaGetSymbolAddress((void**)&ga, g_attn);

    cudaFuncSetAttribute(qkv_gemm, cudaFuncAttributeMaxDynamicSharedMemorySize,
                         GEMM_SMEM);
    cudaFuncSetAttribute(gemm2, cudaFuncAttributeMaxDynamicSharedMemorySize,
                         GEMM_SMEM);
    cudaFuncSetAttribute(attn_mma, cudaFuncAttributeMaxDynamicSharedMemorySize,
                         ATT_SMEM);

    // Fused QKV projections + RoPE (Q pre-scaled for exp2 softmax)
    qkv_gemm<<<dim3(24, 16), 256, GEMM_SMEM>>>(x, rope,
                                               wq_w, wq_b, gq,
                                               wk_w, wk_b, gk,
                                               wv_w, wv_b, gv);

    // Flash attention (exp2 softmax, CVT-free mma, heavy-first)
    attn_mma<<<dim3(S_LEN / ATT_BQ, NH), 256, ATT_SMEM>>>(gq, gk, gv, sinks, ga);

    // Output projection
    gemm2<<<dim3(16, 16), 256, GEMM_SMEM>>>(ga, wo_w, wo_b, out, DIM, NH * HD);
}

// round 15
// speedup vs baseline: 1.1050x; 1.0482x over previous
#include <cuda_runtime.h>
#include <math.h>

#define S_LEN 2048
#define DIM   2048
#define NH    32
#define NKV   8
#define HD    64
#define NREP  4           // NH / NKV
#define QSCALE 0.18033688f   // ATT_SCALE * log2(e)
#define LN2    0.69314718f

// ---------------- scratch (device globals; no allocation allowed) ----------
__device__ float g_q[S_LEN * NH * HD];     // 16 MB
__device__ float g_k[S_LEN * NKV * HD];    // 4 MB
__device__ float g_v[S_LEN * NKV * HD];    // 4 MB
__device__ float g_attn[S_LEN * NH * HD];  // 16 MB  (tf32-rounded by attn)
__device__ float g_x[S_LEN * DIM];         // 16 MB  (tf32-rounded copy of x)

__device__ __forceinline__ unsigned f2tf(float f) {
    unsigned r;
    asm("cvt.rna.tf32.f32 %0, %1;" : "=r"(r) : "f"(f));
    return r;
}
__device__ __forceinline__ float ftf(float f) {
    return __uint_as_float(f2tf(f));
}

__device__ __forceinline__ void cpasync16(void* smem_ptr, const void* gptr) {
    unsigned s = (unsigned)__cvta_generic_to_shared(smem_ptr);
    asm volatile("cp.async.cg.shared.global [%0], [%1], 16;\n" :: "r"(s), "l"(gptr));
}
__device__ __forceinline__ void cp_commit() {
    asm volatile("cp.async.commit_group;\n");
}
__device__ __forceinline__ void cp_wait0() {
    asm volatile("cp.async.wait_group 0;\n");
}
__device__ __forceinline__ void cp_wait1() {
    asm volatile("cp.async.wait_group 1;\n");
}

// ---------------- tf32 round-copy (measured 5.7 us for 16 MB) ---------------
__global__ void round_copy(const float* __restrict__ src, float* __restrict__ dst,
                           int n4)
{
    int i = blockIdx.x * blockDim.x + threadIdx.x;
    if (i >= n4) return;
    float4 v = ((const float4*)src)[i];
    v.x = ftf(v.x); v.y = ftf(v.y); v.z = ftf(v.z); v.w = ftf(v.w);
    ((float4*)dst)[i] = v;
}

// ---------------- TF32 tensor-core GEMM -------------------------------------
// C[M,N] = A[M,K] @ B[N,K]^T + bias[N]; A pre-rounded to tf32 (pure LDS
// A-fragments); B converted per-fragment.
// 128x128 block tile, BK=32, 3-stage cp.async, 8 warps (2x4), warp tile 64x32.
// Epilogue modes: 0 = plain, 1 = fused RoPE (scaled, tf32-rounded),
//                 2 = tf32-rounded.
#define GSTR  36
#define TILEW (128 * GSTR)
#define NSTG  3
#define ESTR  132

__device__ __forceinline__ void gemm_core(
    const float* __restrict__ A, const float* __restrict__ B,
    const float* __restrict__ bias, float* __restrict__ C,
    int N, int K, int m0, int n0, float* sm, int mode,
    const float* __restrict__ rope_g, float oscale)
{
    float* As = sm;
    float* Bs = sm + NSTG * TILEW;

    const int tid  = threadIdx.x;
    const int lane = tid & 31;
    const int w    = tid >> 5;
    const int mw   = (w >> 2) * 64;
    const int nw   = (w & 3) * 32;
    const int g    = lane >> 2;
    const int t    = lane & 3;

    const int lr = tid >> 3;
    const int lc = (tid & 7) << 2;

    float acc[4][4][4];
#pragma unroll
    for (int mt = 0; mt < 4; mt++)
#pragma unroll
        for (int nt = 0; nt < 4; nt++)
#pragma unroll
            for (int r = 0; r < 4; r++) acc[mt][nt][r] = 0.f;

    const int ntiles = K >> 5;

#pragma unroll
    for (int p = 0; p < 2; p++) {
        float* ad = As + p * TILEW;
        float* bd = Bs + p * TILEW;
        const int k0 = p << 5;
#pragma unroll
        for (int i = 0; i < 4; i++) {
            int r = lr + i * 32;
            cpasync16(&ad[r * GSTR + lc], &A[(m0 + r) * K + k0 + lc]);
            cpasync16(&bd[r * GSTR + lc], &B[(n0 + r) * K + k0 + lc]);
        }
        cp_commit();
    }

    int st = 0;
    for (int kt = 0; kt < ntiles; kt++) {
        if (kt + 1 < ntiles) cp_wait1(); else cp_wait0();
        __syncthreads();

        if (kt + 2 < ntiles) {
            const int k0 = (kt + 2) << 5;
            int sn = st + 2; if (sn >= NSTG) sn -= NSTG;
            float* an = As + sn * TILEW;
            float* bn = Bs + sn * TILEW;
#pragma unroll
            for (int i = 0; i < 4; i++) {
                int r = lr + i * 32;
                cpasync16(&an[r * GSTR + lc], &A[(m0 + r) * K + k0 + lc]);
                cpasync16(&bn[r * GSTR + lc], &B[(n0 + r) * K + k0 + lc]);
            }
            cp_commit();
        }

        const unsigned* au = (const unsigned*)(As + st * TILEW);
        const float*    bc = Bs + st * TILEW;
#pragma unroll
        for (int ks = 0; ks < 4; ks++) {
            const int kk = ks * 8;
            unsigned bf[4][2];
#pragma unroll
            for (int nt = 0; nt < 4; nt++) {
                bf[nt][0] = f2tf(bc[(nw + nt * 8 + g) * GSTR + kk + t]);
                bf[nt][1] = f2tf(bc[(nw + nt * 8 + g) * GSTR + kk + 4 + t]);
            }
#pragma unroll
            for (int mt = 0; mt < 4; mt++) {
                unsigned a0 = au[(mw + mt * 16 + g) * GSTR + kk + t];
                unsigned a1 = au[(mw + mt * 16 + 8 + g) * GSTR + kk + t];
                unsigned a2 = au[(mw + mt * 16 + g) * GSTR + kk + 4 + t];
                unsigned a3 = au[(mw + mt * 16 + 8 + g) * GSTR + kk + 4 + t];
#pragma unroll
                for (int nt = 0; nt < 4; nt++) {
                    asm volatile(
                        "mma.sync.aligned.m16n8k8.row.col.f32.tf32.tf32.f32 "
                        "{%0,%1,%2,%3}, {%4,%5,%6,%7}, {%8,%9}, {%0,%1,%2,%3};"
                        : "+f"(acc[mt][nt][0]), "+f"(acc[mt][nt][1]),
                          "+f"(acc[mt][nt][2]), "+f"(acc[mt][nt][3])
                        : "r"(a0), "r"(a1), "r"(a2), "r"(a3),
                          "r"(bf[nt][0]), "r"(bf[nt][1]));
                }
            }
        }
        st++; if (st >= NSTG) st = 0;
    }

    if (mode == 1) {
        // ---- fused RoPE epilogue: stage (acc + bias), rotate, scale, store
        float* stg = sm;
        __syncthreads();
#pragma unroll
        for (int mt = 0; mt < 4; mt++) {
#pragma unroll
            for (int nt = 0; nt < 4; nt++) {
                int row = mw + mt * 16 + g;
                int col = nw + nt * 8 + t * 2;
                float b0 = bias[n0 + col], b1 = bias[n0 + col + 1];
                stg[row * ESTR + col]           = acc[mt][nt][0] + b0;
                stg[row * ESTR + col + 1]       = acc[mt][nt][1] + b1;
                stg[(row + 8) * ESTR + col]     = acc[mt][nt][2] + b0;
                stg[(row + 8) * ESTR + col + 1] = acc[mt][nt][3] + b1;
            }
        }
        __syncthreads();

        for (int i = tid; i < 128 * 64; i += 256) {
            int row = i >> 6;
            int cc  = (i & 63) << 1;
            int d   = cc & 63;
            int s_g = m0 + row;
            if (d < 32) {
                float c0 = rope_g[s_g * HD + d];
                float c1 = rope_g[s_g * HD + d + 1];
                float s0 = rope_g[s_g * HD + 32 + d];
                float s1 = rope_g[s_g * HD + 32 + d + 1];
                float x10 = stg[row * ESTR + cc];
                float x11 = stg[row * ESTR + cc + 1];
                float x20 = stg[row * ESTR + cc + 32];
                float x21 = stg[row * ESTR + cc + 33];
                *(float2*)&C[s_g * N + n0 + cc] =
                    make_float2(ftf((x10 * c0 - x20 * s0) * oscale),
                                ftf((x11 * c1 - x21 * s1) * oscale));
            } else {
                int i0 = d - 32;
                float c0 = rope_g[s_g * HD + i0];
                float c1 = rope_g[s_g * HD + i0 + 1];
                float s0 = rope_g[s_g * HD + 32 + i0];
                float s1 = rope_g[s_g * HD + 32 + i0 + 1];
                float x10 = stg[row * ESTR + cc - 32];
                float x11 = stg[row * ESTR + cc - 31];
                float x20 = stg[row * ESTR + cc];
                float x21 = stg[row * ESTR + cc + 1];
                *(float2*)&C[s_g * N + n0 + cc] =
                    make_float2(ftf((x10 * s0 + x20 * c0) * oscale),
                                ftf((x11 * s1 + x21 * c1) * oscale));
            }
        }
    } else {
#pragma unroll
        for (int mt = 0; mt < 4; mt++) {
#pragma unroll
            for (int nt = 0; nt < 4; nt++) {
                int row = m0 + mw + mt * 16 + g;
                int col = n0 + nw + nt * 8 + t * 2;
                float b0 = bias[col], b1 = bias[col + 1];
                float v0 = acc[mt][nt][0] + b0, v1 = acc[mt][nt][1] + b1;
                float v2 = acc[mt][nt][2] + b0, v3 = acc[mt][nt][3] + b1;
                if (mode == 2) {
                    v0 = ftf(v0); v1 = ftf(v1); v2 = ftf(v2); v3 = ftf(v3);
                }
                *(float2*)&C[row * N + col]       = make_float2(v0, v1);
                *(float2*)&C[(row + 8) * N + col] = make_float2(v2, v3);
            }
        }
    }
}

#define GEMM_SMEM (2 * NSTG * TILEW * (int)sizeof(float))   // 110592 B

__global__ void __launch_bounds__(256)
qkv_gemm(const float* __restrict__ x, const float* __restrict__ rope_g,
         const float* __restrict__ wq, const float* __restrict__ bq, float* __restrict__ oq,
         const float* __restrict__ wk, const float* __restrict__ bk, float* __restrict__ ok,
         const float* __restrict__ wv, const float* __restrict__ bv, float* __restrict__ ov)
{
    extern __shared__ float sm[];
    const int bx = blockIdx.x;
    const float *B, *bias; float* C; int N, n0, mode; float osc;
    if (bx < 16)      { B = wq; bias = bq; C = oq; N = 2048; n0 = bx * 128;
                        mode = 1; osc = QSCALE; }
    else if (bx < 20) { B = wk; bias = bk; C = ok; N = 512;  n0 = (bx - 16) * 128;
                        mode = 1; osc = 1.0f; }
    else              { B = wv; bias = bv; C = ov; N = 512;  n0 = (bx - 20) * 128;
                        mode = 2; osc = 1.0f; }
    gemm_core(x, B, bias, C, N, DIM, blockIdx.y * 128, n0, sm, mode, rope_g, osc);
}

__global__ void __launch_bounds__(256)
gemm2(const float* __restrict__ A, const float* __restrict__ B,
      const float* __restrict__ bias, float* __restrict__ C, int N, int K)
{
    extern __shared__ float sm[];
    gemm_core(A, B, bias, C, N, K, blockIdx.y * 128, blockIdx.x * 128, sm, 0,
              (const float*)0, 1.0f);
}

// ---------------- Flash attention: exp2 softmax, CVT-free mma ---------------
// BQ=256, BKV=64, 8 warps x 32 q-rows, cp.async double-buffered K/V + Q.
// Q pre-scaled by ATT_SCALE*log2(e); O written tf32-rounded (gemm2's A).
#define QSTR 68
#define KSTR 68
#define VST2 72
#define PSTR 68
#define ATT_BQ 256
#define ATT_BK 64

#define ATT_SMEM ((ATT_BQ * QSTR + 2 * ATT_BK * KSTR + 2 * ATT_BK * VST2 \
                   + ATT_BQ * PSTR) * (int)sizeof(unsigned))   // 210944 B

__global__ void __launch_bounds__(256)
attn_mma(const float* __restrict__ Q, const float* __restrict__ K,
         const float* __restrict__ V, const float* __restrict__ sinks,
         float* __restrict__ O)
{
    extern __shared__ unsigned sm_u[];
    unsigned* q_s = sm_u;
    float*    k_s = (float*)(q_s + ATT_BQ * QSTR);
    float*    v_s = k_s + 2 * ATT_BK * KSTR;
    unsigned* p_s = (unsigned*)(v_s + 2 * ATT_BK * VST2);

    const int h    = blockIdx.y;
    const int q0   = (gridDim.x - 1 - blockIdx.x) * ATT_BQ;
    const int kvh  = h >> 2;
    const int tid  = threadIdx.x;
    const int lane = tid & 31;
    const int w    = tid >> 5;
    const int g    = lane >> 2;
    const int t    = lane & 3;
    const int mw   = w * 32;

    const int ntiles = q0 / ATT_BK + 4;

#pragma unroll
    for (int i = 0; i < 16; i++) {
        int idx = tid + i * 256;
        int row = idx >> 4, c4 = (idx & 15) << 2;
        cpasync16(&q_s[row * QSTR + c4], &Q[(q0 + row) * (NH * HD) + h * HD + c4]);
    }
    cp_commit();
#pragma unroll
    for (int p = 0; p < 2; p++) {
        const int k0 = p * ATT_BK;
        float* kd = k_s + p * ATT_BK * KSTR;
        float* vd = v_s + p * ATT_BK * VST2;
#pragma unroll
        for (int i = 0; i < 4; i++) {
            int idx = tid + i * 256;
            int row = idx >> 4, c4 = (idx & 15) << 2;
            cpasync16(&kd[row * KSTR + c4], &K[(k0 + row) * (NKV * HD) + kvh * HD + c4]);
            cpasync16(&vd[row * VST2 + c4], &V[(k0 + row) * (NKV * HD) + kvh * HD + c4]);
        }
        cp_commit();
    }

    float o[2][8][4];
#pragma unroll
    for (int mt = 0; mt < 2; mt++)
#pragma unroll
        for (int nt = 0; nt < 8; nt++)
#pragma unroll
            for (int r = 0; r < 4; r++) o[mt][nt][r] = 0.f;
    float m_st[2][2], l_st[2][2];
#pragma unroll
    for (int mt = 0; mt < 2; mt++) {
        m_st[mt][0] = -INFINITY; m_st[mt][1] = -INFINITY;
        l_st[mt][0] = 0.f;       l_st[mt][1] = 0.f;
    }

    for (int kt = 0; kt < ntiles; kt++) {
        const int k0 = kt * ATT_BK;
        if (kt + 1 < ntiles) cp_wait1(); else cp_wait0();
        __syncthreads();

        const unsigned* kc = (const unsigned*)(k_s + (kt & 1) * ATT_BK * KSTR);
        const unsigned* vc = (const unsigned*)(v_s + (kt & 1) * ATT_BK * VST2);

        const bool active = (k0 <= q0 + mw + 31);
        if (active) {
            float s[2][8][4];
#pragma unroll
            for (int mt = 0; mt < 2; mt++)
#pragma unroll
                for (int nt = 0; nt < 8; nt++)
#pragma unroll
                    for (int r = 0; r < 4; r++) s[mt][nt][r] = 0.f;

#pragma unroll
            for (int ks = 0; ks < 8; ks++) {
                const int kk = ks * 8;
                unsigned a[2][4];
#pragma unroll
                for (int mt = 0; mt < 2; mt++) {
                    const int rb = (mw + mt * 16 + g) * QSTR;
                    a[mt][0] = q_s[rb + kk + t];
                    a[mt][1] = q_s[rb + 8 * QSTR + kk + t];
                    a[mt][2] = q_s[rb + kk + 4 + t];
                    a[mt][3] = q_s[rb + 8 * QSTR + kk + 4 + t];
                }
#pragma unroll
                for (int nt = 0; nt < 8; nt++) {
                    unsigned b0 = kc[(nt * 8 + g) * KSTR + kk + t];
                    unsigned b1 = kc[(nt * 8 + g) * KSTR + kk + 4 + t];
#pragma unroll
                    for (int mt = 0; mt < 2; mt++) {
                        asm volatile(
                            "mma.sync.aligned.m16n8k8.row.col.f32.tf32.tf32.f32 "
                            "{%0,%1,%2,%3}, {%4,%5,%6,%7}, {%8,%9}, {%0,%1,%2,%3};"
                            : "+f"(s[mt][nt][0]), "+f"(s[mt][nt][1]),
                              "+f"(s[mt][nt][2]), "+f"(s[mt][nt][3])
                            : "r"(a[mt][0]), "r"(a[mt][1]), "r"(a[mt][2]), "r"(a[mt][3]),
                              "r"(b0), "r"(b1));
                    }
                }
            }

            if (k0 + ATT_BK - 1 > q0 + mw) {
#pragma unroll
                for (int mt = 0; mt < 2; mt++) {
                    int qa = q0 + mw + mt * 16 + g;
                    int qb = qa + 8;
#pragma unroll
                    for (int nt = 0; nt < 8; nt++) {
                        int kg0 = k0 + nt * 8 + 2 * t;
                        if (kg0     > qa) s[mt][nt][0] = -1e30f;
                        if (kg0 + 1 > qa) s[mt][nt][1] = -1e30f;
                        if (kg0     > qb) s[mt][nt][2] = -1e30f;
                        if (kg0 + 1 > qb) s[mt][nt][3] = -1e30f;
                    }
                }
            }

#pragma unroll
            for (int mt = 0; mt < 2; mt++) {
                float mlA = -INFINITY, mlB = -INFINITY;
#pragma unroll
                for (int nt = 0; nt < 8; nt++) {
                    mlA = fmaxf(mlA, fmaxf(s[mt][nt][0], s[mt][nt][1]));
                    mlB = fmaxf(mlB, fmaxf(s[mt][nt][2], s[mt][nt][3]));
                }
                mlA = fmaxf(mlA, __shfl_xor_sync(0xffffffffu, mlA, 1));
                mlA = fmaxf(mlA, __shfl_xor_sync(0xffffffffu, mlA, 2));
                mlB = fmaxf(mlB, __shfl_xor_sync(0xffffffffu, mlB, 1));
                mlB = fmaxf(mlB, __shfl_xor_sync(0xffffffffu, mlB, 2));

                float mnA = fmaxf(m_st[mt][0], mlA);
                float mnB = fmaxf(m_st[mt][1], mlB);
                float alA = exp2f(m_st[mt][0] - mnA);
                float alB = exp2f(m_st[mt][1] - mnB);

                float sumA = 0.f, sumB = 0.f;
                const int rbA = (mw + mt * 16 + g) * PSTR;
                const int rbB = rbA + 8 * PSTR;
#pragma unroll
                for (int nt = 0; nt < 8; nt++) {
                    float p0 = exp2f(s[mt][nt][0] - mnA);
                    float p1 = exp2f(s[mt][nt][1] - mnA);
                    float p2 = exp2f(s[mt][nt][2] - mnB);
                    float p3 = exp2f(s[mt][nt][3] - mnB);
                    sumA += p0 + p1;
                    sumB += p2 + p3;
                    int col = nt * 8 + 2 * t;
                    *(uint2*)&p_s[rbA + col] = make_uint2(f2tf(p0), f2tf(p1));
                    *(uint2*)&p_s[rbB + col] = make_uint2(f2tf(p2), f2tf(p3));
                }
                sumA += __shfl_xor_sync(0xffffffffu, sumA, 1);
                sumA += __shfl_xor_sync(0xffffffffu, sumA, 2);
                sumB += __shfl_xor_sync(0xffffffffu, sumB, 1);
                sumB += __shfl_xor_sync(0xffffffffu, sumB, 2);

                l_st[mt][0] = l_st[mt][0] * alA + sumA;  m_st[mt][0] = mnA;
                l_st[mt][1] = l_st[mt][1] * alB + sumB;  m_st[mt][1] = mnB;

#pragma unroll
                for (int nt = 0; nt < 8; nt++) {
                    o[mt][nt][0] *= alA; o[mt][nt][1] *= alA;
                    o[mt][nt][2] *= alB; o[mt][nt][3] *= alB;
                }
            }

            __syncwarp();

#pragma unroll
            for (int ks = 0; ks < 8; ks++) {
                const int kk = ks * 8;
                unsigned a[2][4];
#pragma unroll
                for (int mt = 0; mt < 2; mt++) {
                    const int rb = (mw + mt * 16 + g) * PSTR;
                    a[mt][0] = p_s[rb + kk + t];
                    a[mt][1] = p_s[rb + 8 * PSTR + kk + t];
                    a[mt][2] = p_s[rb + kk + 4 + t];
                    a[mt][3] = p_s[rb + 8 * PSTR + kk + 4 + t];
                }
#pragma unroll
                for (int nt = 0; nt < 8; nt++) {
                    unsigned b0 = vc[(kk + t) * VST2 + nt * 8 + g];
                    unsigned b1 = vc[(kk + 4 + t) * VST2 + nt * 8 + g];
#pragma unroll
                    for (int mt = 0; mt < 2; mt++) {
                        asm volatile(
                            "mma.sync.aligned.m16n8k8.row.col.f32.tf32.tf32.f32 "
                            "{%0,%1,%2,%3}, {%4,%5,%6,%7}, {%8,%9}, {%0,%1,%2,%3};"
                            : "+f"(o[mt][nt][0]), "+f"(o[mt][nt][1]),
                              "+f"(o[mt][nt][2]), "+f"(o[mt][nt][3])
                            : "r"(a[mt][0]), "r"(a[mt][1]), "r"(a[mt][2]), "r"(a[mt][3]),
                              "r"(b0), "r"(b1));
                    }
                }
            }
        }
        __syncthreads();

        if (kt + 2 < ntiles) {
            const int kn = (kt + 2) * ATT_BK;
            float* kd = k_s + (kt & 1) * ATT_BK * KSTR;
            float* vd = v_s + (kt & 1) * ATT_BK * VST2;
#pragma unroll
            for (int i = 0; i < 4; i++) {
                int idx = tid + i * 256;
                int row = idx >> 4, c4 = (idx & 15) << 2;
                cpasync16(&kd[row * KSTR + c4], &K[(kn + row) * (NKV * HD) + kvh * HD + c4]);
                cpasync16(&vd[row * VST2 + c4], &V[(kn + row) * (NKV * HD) + kvh * HD + c4]);
            }
            cp_commit();
        }
    }

    // ---- epilogue: normalize + sink scale; write tf32-rounded O ----
    float snk = sinks[h];
#pragma unroll
    for (int mt = 0; mt < 2; mt++) {
        int qa = q0 + mw + mt * 16 + g;
        int qb = qa + 8;
        float lseA = (m_st[mt][0] + __log2f(l_st[mt][0])) * LN2;
        float lseB = (m_st[mt][1] + __log2f(l_st[mt][1])) * LN2;
        float invA = (1.f / (1.f + __expf(-(lseA - snk)))) / l_st[mt][0];
        float invB = (1.f / (1.f + __expf(-(lseB - snk)))) / l_st[mt][1];
#pragma unroll
        for (int nt = 0; nt < 8; nt++) {
            int col = nt * 8 + 2 * t;
            *(float2*)&O[qa * (NH * HD) + h * HD + col] =
                make_float2(ftf(o[mt][nt][0] * invA), ftf(o[mt][nt][1] * invA));
            *(float2*)&O[qb * (NH * HD) + h * HD + col] =
                make_float2(ftf(o[mt][nt][2] * invB), ftf(o[mt][nt][3] * invB));
        }
    }
}

// ---------------- launch ----------------------------------------------------
extern "C" void kernel_launch(void* const* d_in, const int* in_sizes, int n_in,
                              void* d_out, int out_size)
{
    const float* x     = (const float*)d_in[0];
    const float* rope  = (const float*)d_in[1];
    const float* wq_w  = (const float*)d_in[2];
    const float* wq_b  = (const float*)d_in[3];
    const float* wk_w  = (const float*)d_in[4];
    const float* wk_b  = (const float*)d_in[5];
    const float* wv_w  = (const float*)d_in[6];
    const float* wv_b  = (const float*)d_in[7];
    const float* wo_w  = (const float*)d_in[8];
    const float* wo_b  = (const float*)d_in[9];
    const float* sinks = (const float*)d_in[10];
    float* out = (float*)d_out;

    float *gq, *gk, *gv, *ga, *gx;
    cudaGetSymbolAddress((void**)&gq, g_q);
    cudaGetSymbolAddress((void**)&gk, g_k);
    cudaGetSymbolAddress((void**)&gv, g_v);
    cudaGetSymbolAddress((void**)&ga, g_attn);
    cudaGetSymbolAddress((void**)&gx, g_x);

    cudaFuncSetAttribute(qkv_gemm, cudaFuncAttributeMaxDynamicSharedMemorySize,
                         GEMM_SMEM);
    cudaFuncSetAttribute(gemm2, cudaFuncAttributeMaxDynamicSharedMemorySize,
                         GEMM_SMEM);
    cudaFuncSetAttribute(attn_mma, cudaFuncAttributeMaxDynamicSharedMemorySize,
                         ATT_SMEM);

    // tf32 round-copy of x (16 MB, ~6 us) -> CVT-free A-side in qkv_gemm
    const int n4 = (S_LEN * DIM) / 4;
    round_copy<<<(n4 + 255) / 256, 256>>>(x, gx, n4);

    // Fused QKV projections + RoPE (Q pre-scaled for exp2 softmax)
    qkv_gemm<<<dim3(24, 16), 256, GEMM_SMEM>>>(gx, rope,
                                               wq_w, wq_b, gq,
                                               wk_w, wk_b, gk,
                                               wv_w, wv_b, gv);

    // Flash attention (exp2 softmax, CVT-free mma, heavy-first, rounded O)
    attn_mma<<<dim3(S_LEN / ATT_BQ, NH), 256, ATT_SMEM>>>(gq, gk, gv, sinks, ga);

    // Output projection (A = g_attn pre-rounded -> CVT-free A-side)
    gemm2<<<dim3(16, 16), 256, GEMM_SMEM>>>(ga, wo_w, wo_b, out, DIM, NH * HD);
}

// round 16
// speedup vs baseline: 1.1132x; 1.0074x over previous
#include <cuda_runtime.h>
#include <math.h>

#define S_LEN 2048
#define DIM   2048
#define NH    32
#define NKV   8
#define HD    64
#define NREP  4           // NH / NKV
#define QSCALE 0.18033688f   // ATT_SCALE * log2(e)
#define LN2    0.69314718f

// ---------------- scratch (device globals; no allocation allowed) ----------
__device__ float g_q[S_LEN * NH * HD];     // 16 MB
__device__ float g_k[S_LEN * NKV * HD];    // 4 MB
__device__ float g_v[S_LEN * NKV * HD];    // 4 MB
__device__ float g_attn[S_LEN * NH * HD];  // 16 MB  (tf32-rounded by attn)
__device__ float g_x[S_LEN * DIM];         // 16 MB  (tf32-rounded copy of x)

__device__ __forceinline__ unsigned f2tf(float f) {
    unsigned r;
    asm("cvt.rna.tf32.f32 %0, %1;" : "=r"(r) : "f"(f));
    return r;
}
__device__ __forceinline__ float ftf(float f) {
    return __uint_as_float(f2tf(f));
}

__device__ __forceinline__ void cpasync16(void* smem_ptr, const void* gptr) {
    unsigned s = (unsigned)__cvta_generic_to_shared(smem_ptr);
    asm volatile("cp.async.cg.shared.global [%0], [%1], 16;\n" :: "r"(s), "l"(gptr));
}
__device__ __forceinline__ void cp_commit() {
    asm volatile("cp.async.commit_group;\n");
}
__device__ __forceinline__ void cp_wait0() {
    asm volatile("cp.async.wait_group 0;\n");
}
__device__ __forceinline__ void cp_wait1() {
    asm volatile("cp.async.wait_group 1;\n");
}

// ---------------- tf32 round-copy -------------------------------------------
__global__ void round_copy(const float* __restrict__ src, float* __restrict__ dst,
                           int n4)
{
    int i = blockIdx.x * blockDim.x + threadIdx.x;
    if (i >= n4) return;
    float4 v = ((const float4*)src)[i];
    v.x = ftf(v.x); v.y = ftf(v.y); v.z = ftf(v.z); v.w = ftf(v.w);
    ((float4*)dst)[i] = v;
}

// ---------------- TF32 tensor-core GEMM: NSTG=2, 3 CTAs/SM ------------------
// C[M,N] = A[M,K] @ B[N,K]^T + bias[N]; A pre-rounded to tf32 (pure LDS
// A-fragments); B converted per-fragment.
// 128x128 block tile, BK=32, double-buffered cp.async (round-4 structure),
// 8 warps (2x4), warp tile 64x32. smem 73728 B -> 3 CTAs/SM (24 warps).
// Epilogue modes: 0 = plain, 1 = fused RoPE (scaled, tf32-rounded),
//                 2 = tf32-rounded.
#define GSTR  36
#define TILEW (128 * GSTR)
#define ESTR  132

__device__ __forceinline__ void gemm_core(
    const float* __restrict__ A, const float* __restrict__ B,
    const float* __restrict__ bias, float* __restrict__ C,
    int N, int K, int m0, int n0, float* sm, int mode,
    const float* __restrict__ rope_g, float oscale)
{
    float* As = sm;                  // [2][128][GSTR]
    float* Bs = sm + 2 * TILEW;      // [2][128][GSTR]

    const int tid  = threadIdx.x;
    const int lane = tid & 31;
    const int w    = tid >> 5;
    const int mw   = (w >> 2) * 64;
    const int nw   = (w & 3) * 32;
    const int g    = lane >> 2;
    const int t    = lane & 3;

    const int lr = tid >> 3;
    const int lc = (tid & 7) << 2;

    float acc[4][4][4];
#pragma unroll
    for (int mt = 0; mt < 4; mt++)
#pragma unroll
        for (int nt = 0; nt < 4; nt++)
#pragma unroll
            for (int r = 0; r < 4; r++) acc[mt][nt][r] = 0.f;

    const int ntiles = K >> 5;

    // ---- prologue: stage 0 ----
#pragma unroll
    for (int i = 0; i < 4; i++) {
        int r = lr + i * 32;
        cpasync16(&As[r * GSTR + lc], &A[(m0 + r) * K + lc]);
        cpasync16(&Bs[r * GSTR + lc], &B[(n0 + r) * K + lc]);
    }
    cp_commit();
    cp_wait0();
    __syncthreads();

    int st = 0;
    for (int kt = 0; kt < ntiles; kt++) {
        // issue next tile into the other buffer (overlaps with compute)
        if (kt + 1 < ntiles) {
            const int k0 = (kt + 1) << 5;
            float* an = As + (st ^ 1) * TILEW;
            float* bn = Bs + (st ^ 1) * TILEW;
#pragma unroll
            for (int i = 0; i < 4; i++) {
                int r = lr + i * 32;
                cpasync16(&an[r * GSTR + lc], &A[(m0 + r) * K + k0 + lc]);
                cpasync16(&bn[r * GSTR + lc], &B[(n0 + r) * K + k0 + lc]);
            }
            cp_commit();
        }

        const unsigned* au = (const unsigned*)(As + st * TILEW);
        const float*    bc = Bs + st * TILEW;
#pragma unroll
        for (int ks = 0; ks < 4; ks++) {
            const int kk = ks * 8;
            unsigned bf[4][2];
#pragma unroll
            for (int nt = 0; nt < 4; nt++) {
                bf[nt][0] = f2tf(bc[(nw + nt * 8 + g) * GSTR + kk + t]);
                bf[nt][1] = f2tf(bc[(nw + nt * 8 + g) * GSTR + kk + 4 + t]);
            }
#pragma unroll
            for (int mt = 0; mt < 4; mt++) {
                unsigned a0 = au[(mw + mt * 16 + g) * GSTR + kk + t];
                unsigned a1 = au[(mw + mt * 16 + 8 + g) * GSTR + kk + t];
                unsigned a2 = au[(mw + mt * 16 + g) * GSTR + kk + 4 + t];
                unsigned a3 = au[(mw + mt * 16 + 8 + g) * GSTR + kk + 4 + t];
#pragma unroll
                for (int nt = 0; nt < 4; nt++) {
                    asm volatile(
                        "mma.sync.aligned.m16n8k8.row.col.f32.tf32.tf32.f32 "
                        "{%0,%1,%2,%3}, {%4,%5,%6,%7}, {%8,%9}, {%0,%1,%2,%3};"
                        : "+f"(acc[mt][nt][0]), "+f"(acc[mt][nt][1]),
                          "+f"(acc[mt][nt][2]), "+f"(acc[mt][nt][3])
                        : "r"(a0), "r"(a1), "r"(a2), "r"(a3),
                          "r"(bf[nt][0]), "r"(bf[nt][1]));
                }
            }
        }

        if (kt + 1 < ntiles) cp_wait0();
        __syncthreads();
        st ^= 1;
    }

    if (mode == 1) {
        // ---- fused RoPE epilogue: stage (acc + bias), rotate, scale, store
        float* stg = sm;   // 128*ESTR*4 = 67584 B <= 73728 B
#pragma unroll
        for (int mt = 0; mt < 4; mt++) {
#pragma unroll
            for (int nt = 0; nt < 4; nt++) {
                int row = mw + mt * 16 + g;
                int col = nw + nt * 8 + t * 2;
                float b0 = bias[n0 + col], b1 = bias[n0 + col + 1];
                stg[row * ESTR + col]           = acc[mt][nt][0] + b0;
                stg[row * ESTR + col + 1]       = acc[mt][nt][1] + b1;
                stg[(row + 8) * ESTR + col]     = acc[mt][nt][2] + b0;
                stg[(row + 8) * ESTR + col + 1] = acc[mt][nt][3] + b1;
            }
        }
        __syncthreads();

        for (int i = tid; i < 128 * 64; i += 256) {
            int row = i >> 6;
            int cc  = (i & 63) << 1;
            int d   = cc & 63;
            int s_g = m0 + row;
            if (d < 32) {
                float c0 = rope_g[s_g * HD + d];
                float c1 = rope_g[s_g * HD + d + 1];
                float s0 = rope_g[s_g * HD + 32 + d];
                float s1 = rope_g[s_g * HD + 32 + d + 1];
                float x10 = stg[row * ESTR + cc];
                float x11 = stg[row * ESTR + cc + 1];
                float x20 = stg[row * ESTR + cc + 32];
                float x21 = stg[row * ESTR + cc + 33];
                *(float2*)&C[s_g * N + n0 + cc] =
                    make_float2(ftf((x10 * c0 - x20 * s0) * oscale),
                                ftf((x11 * c1 - x21 * s1) * oscale));
            } else {
                int i0 = d - 32;
                float c0 = rope_g[s_g * HD + i0];
                float c1 = rope_g[s_g * HD + i0 + 1];
                float s0 = rope_g[s_g * HD + 32 + i0];
                float s1 = rope_g[s_g * HD + 32 + i0 + 1];
                float x10 = stg[row * ESTR + cc - 32];
                float x11 = stg[row * ESTR + cc - 31];
                float x20 = stg[row * ESTR + cc];
                float x21 = stg[row * ESTR + cc + 1];
                *(float2*)&C[s_g * N + n0 + cc] =
                    make_float2(ftf((x10 * s0 + x20 * c0) * oscale),
                                ftf((x11 * s1 + x21 * c1) * oscale));
            }
        }
    } else {
#pragma unroll
        for (int mt = 0; mt < 4; mt++) {
#pragma unroll
            for (int nt = 0; nt < 4; nt++) {
                int row = m0 + mw + mt * 16 + g;
                int col = n0 + nw + nt * 8 + t * 2;
                float b0 = bias[col], b1 = bias[col + 1];
                float v0 = acc[mt][nt][0] + b0, v1 = acc[mt][nt][1] + b1;
                float v2 = acc[mt][nt][2] + b0, v3 = acc[mt][nt][3] + b1;
                if (mode == 2) {
                    v0 = ftf(v0); v1 = ftf(v1); v2 = ftf(v2); v3 = ftf(v3);
                }
                *(float2*)&C[row * N + col]       = make_float2(v0, v1);
                *(float2*)&C[(row + 8) * N + col] = make_float2(v2, v3);
            }
        }
    }
}

#define GEMM_SMEM (4 * TILEW * (int)sizeof(float))   // 73728 B -> 3 CTAs/SM

__global__ void __launch_bounds__(256)
qkv_gemm(const float* __restrict__ x, const float* __restrict__ rope_g,
         const float* __restrict__ wq, const float* __restrict__ bq, float* __restrict__ oq,
         const float* __restrict__ wk, const float* __restrict__ bk, float* __restrict__ ok,
         const float* __restrict__ wv, const float* __restrict__ bv, float* __restrict__ ov)
{
    extern __shared__ float sm[];
    const int bx = blockIdx.x;
    const float *B, *bias; float* C; int N, n0, mode; float osc;
    if (bx < 16)      { B = wq; bias = bq; C = oq; N = 2048; n0 = bx * 128;
                        mode = 1; osc = QSCALE; }
    else if (bx < 20) { B = wk; bias = bk; C = ok; N = 512;  n0 = (bx - 16) * 128;
                        mode = 1; osc = 1.0f; }
    else              { B = wv; bias = bv; C = ov; N = 512;  n0 = (bx - 20) * 128;
                        mode = 2; osc = 1.0f; }
    gemm_core(x, B, bias, C, N, DIM, blockIdx.y * 128, n0, sm, mode, rope_g, osc);
}

__global__ void __launch_bounds__(256)
gemm2(const float* __restrict__ A, const float* __restrict__ B,
      const float* __restrict__ bias, float* __restrict__ C, int N, int K)
{
    extern __shared__ float sm[];
    gemm_core(A, B, bias, C, N, K, blockIdx.y * 128, blockIdx.x * 128, sm, 0,
              (const float*)0, 1.0f);
}

// ---------------- Flash attention: exp2 softmax, CVT-free mma ---------------
// BQ=256, BKV=64, 8 warps x 32 q-rows, cp.async double-buffered K/V + Q.
// Q pre-scaled by ATT_SCALE*log2(e); O written tf32-rounded (gemm2's A).
#define QSTR 68
#define KSTR 68
#define VST2 72
#define PSTR 68
#define ATT_BQ 256
#define ATT_BK 64

#define ATT_SMEM ((ATT_BQ * QSTR + 2 * ATT_BK * KSTR + 2 * ATT_BK * VST2 \
                   + ATT_BQ * PSTR) * (int)sizeof(unsigned))   // 210944 B

__global__ void __launch_bounds__(256)
attn_mma(const float* __restrict__ Q, const float* __restrict__ K,
         const float* __restrict__ V, const float* __restrict__ sinks,
         float* __restrict__ O)
{
    extern __shared__ unsigned sm_u[];
    unsigned* q_s = sm_u;
    float*    k_s = (float*)(q_s + ATT_BQ * QSTR);
    float*    v_s = k_s + 2 * ATT_BK * KSTR;
    unsigned* p_s = (unsigned*)(v_s + 2 * ATT_BK * VST2);

    const int h    = blockIdx.y;
    const int q0   = (gridDim.x - 1 - blockIdx.x) * ATT_BQ;
    const int kvh  = h >> 2;
    const int tid  = threadIdx.x;
    const int lane = tid & 31;
    const int w    = tid >> 5;
    const int g    = lane >> 2;
    const int t    = lane & 3;
    const int mw   = w * 32;

    const int ntiles = q0 / ATT_BK + 4;

#pragma unroll
    for (int i = 0; i < 16; i++) {
        int idx = tid + i * 256;
        int row = idx >> 4, c4 = (idx & 15) << 2;
        cpasync16(&q_s[row * QSTR + c4], &Q[(q0 + row) * (NH * HD) + h * HD + c4]);
    }
    cp_commit();
#pragma unroll
    for (int p = 0; p < 2; p++) {
        const int k0 = p * ATT_BK;
        float* kd = k_s + p * ATT_BK * KSTR;
        float* vd = v_s + p * ATT_BK * VST2;
#pragma unroll
        for (int i = 0; i < 4; i++) {
            int idx = tid + i * 256;
            int row = idx >> 4, c4 = (idx & 15) << 2;
            cpasync16(&kd[row * KSTR + c4], &K[(k0 + row) * (NKV * HD) + kvh * HD + c4]);
            cpasync16(&vd[row * VST2 + c4], &V[(k0 + row) * (NKV * HD) + kvh * HD + c4]);
        }
        cp_commit();
    }

    float o[2][8][4];
#pragma unroll
    for (int mt = 0; mt < 2; mt++)
#pragma unroll
        for (int nt = 0; nt < 8; nt++)
#pragma unroll
            for (int r = 0; r < 4; r++) o[mt][nt][r] = 0.f;
    float m_st[2][2], l_st[2][2];
#pragma unroll
    for (int mt = 0; mt < 2; mt++) {
        m_st[mt][0] = -INFINITY; m_st[mt][1] = -INFINITY;
        l_st[mt][0] = 0.f;       l_st[mt][1] = 0.f;
    }

    for (int kt = 0; kt < ntiles; kt++) {
        const int k0 = kt * ATT_BK;
        if (kt + 1 < ntiles) cp_wait1(); else cp_wait0();
        __syncthreads();

        const unsigned* kc = (const unsigned*)(k_s + (kt & 1) * ATT_BK * KSTR);
        const unsigned* vc = (const unsigned*)(v_s + (kt & 1) * ATT_BK * VST2);

        const bool active = (k0 <= q0 + mw + 31);
        if (active) {
            float s[2][8][4];
#pragma unroll
            for (int mt = 0; mt < 2; mt++)
#pragma unroll
                for (int nt = 0; nt < 8; nt++)
#pragma unroll
                    for (int r = 0; r < 4; r++) s[mt][nt][r] = 0.f;

#pragma unroll
            for (int ks = 0; ks < 8; ks++) {
                const int kk = ks * 8;
                unsigned a[2][4];
#pragma unroll
                for (int mt = 0; mt < 2; mt++) {
                    const int rb = (mw + mt * 16 + g) * QSTR;
                    a[mt][0] = q_s[rb + kk + t];
                    a[mt][1] = q_s[rb + 8 * QSTR + kk + t];
                    a[mt][2] = q_s[rb + kk + 4 + t];
                    a[mt][3] = q_s[rb + 8 * QSTR + kk + 4 + t];
                }
#pragma unroll
                for (int nt = 0; nt < 8; nt++) {
                    unsigned b0 = kc[(nt * 8 + g) * KSTR + kk + t];
                    unsigned b1 = kc[(nt * 8 + g) * KSTR + kk + 4 + t];
#pragma unroll
                    for (int mt = 0; mt < 2; mt++) {
                        asm volatile(
                            "mma.sync.aligned.m16n8k8.row.col.f32.tf32.tf32.f32 "
                            "{%0,%1,%2,%3}, {%4,%5,%6,%7}, {%8,%9}, {%0,%1,%2,%3};"
                            : "+f"(s[mt][nt][0]), "+f"(s[mt][nt][1]),
                              "+f"(s[mt][nt][2]), "+f"(s[mt][nt][3])
                            : "r"(a[mt][0]), "r"(a[mt][1]), "r"(a[mt][2]), "r"(a[mt][3]),
                              "r"(b0), "r"(b1));
                    }
                }
            }

            if (k0 + ATT_BK - 1 > q0 + mw) {
#pragma unroll
                for (int mt = 0; mt < 2; mt++) {
                    int qa = q0 + mw + mt * 16 + g;
                    int qb = qa + 8;
#pragma unroll
                    for (int nt = 0; nt < 8; nt++) {
                        int kg0 = k0 + nt * 8 + 2 * t;
                        if (kg0     > qa) s[mt][nt][0] = -1e30f;
                        if (kg0 + 1 > qa) s[mt][nt][1] = -1e30f;
                        if (kg0     > qb) s[mt][nt][2] = -1e30f;
                        if (kg0 + 1 > qb) s[mt][nt][3] = -1e30f;
                    }
                }
            }

#pragma unroll
            for (int mt = 0; mt < 2; mt++) {
                float mlA = -INFINITY, mlB = -INFINITY;
#pragma unroll
                for (int nt = 0; nt < 8; nt++) {
                    mlA = fmaxf(mlA, fmaxf(s[mt][nt][0], s[mt][nt][1]));
                    mlB = fmaxf(mlB, fmaxf(s[mt][nt][2], s[mt][nt][3]));
                }
                mlA = fmaxf(mlA, __shfl_xor_sync(0xffffffffu, mlA, 1));
                mlA = fmaxf(mlA, __shfl_xor_sync(0xffffffffu, mlA, 2));
                mlB = fmaxf(mlB, __shfl_xor_sync(0xffffffffu, mlB, 1));
                mlB = fmaxf(mlB, __shfl_xor_sync(0xffffffffu, mlB, 2));

                float mnA = fmaxf(m_st[mt][0], mlA);
                float mnB = fmaxf(m_st[mt][1], mlB);
                float alA = exp2f(m_st[mt][0] - mnA);
                float alB = exp2f(m_st[mt][1] - mnB);

                float sumA = 0.f, sumB = 0.f;
                const int rbA = (mw + mt * 16 + g) * PSTR;
                const int rbB = rbA + 8 * PSTR;
#pragma unroll
                for (int nt = 0; nt < 8; nt++) {
                    float p0 = exp2f(s[mt][nt][0] - mnA);
                    float p1 = exp2f(s[mt][nt][1] - mnA);
                    float p2 = exp2f(s[mt][nt][2] - mnB);
                    float p3 = exp2f(s[mt][nt][3] - mnB);
                    sumA += p0 + p1;
                    sumB += p2 + p3;
                    int col = nt * 8 + 2 * t;
                    *(uint2*)&p_s[rbA + col] = make_uint2(f2tf(p0), f2tf(p1));
                    *(uint2*)&p_s[rbB + col] = make_uint2(f2tf(p2), f2tf(p3));
                }
                sumA += __shfl_xor_sync(0xffffffffu, sumA, 1);
                sumA += __shfl_xor_sync(0xffffffffu, sumA, 2);
                sumB += __shfl_xor_sync(0xffffffffu, sumB, 1);
                sumB += __shfl_xor_sync(0xffffffffu, sumB, 2);

                l_st[mt][0] = l_st[mt][0] * alA + sumA;  m_st[mt][0] = mnA;
                l_st[mt][1] = l_st[mt][1] * alB + sumB;  m_st[mt][1] = mnB;

#pragma unroll
                for (int nt = 0; nt < 8; nt++) {
                    o[mt][nt][0] *= alA; o[mt][nt][1] *= alA;
                    o[mt][nt][2] *= alB; o[mt][nt][3] *= alB;
                }
            }

            __syncwarp();

#pragma unroll
            for (int ks = 0; ks < 8; ks++) {
                const int kk = ks * 8;
                unsigned a[2][4];
#pragma unroll
                for (int mt = 0; mt < 2; mt++) {
                    const int rb = (mw + mt * 16 + g) * PSTR;
                    a[mt][0] = p_s[rb + kk + t];
                    a[mt][1] = p_s[rb + 8 * PSTR + kk + t];
                    a[mt][2] = p_s[rb + kk + 4 + t];
                    a[mt][3] = p_s[rb + 8 * PSTR + kk + 4 + t];
                }
#pragma unroll
                for (int nt = 0; nt < 8; nt++) {
                    unsigned b0 = vc[(kk + t) * VST2 + nt * 8 + g];
                    unsigned b1 = vc[(kk + 4 + t) * VST2 + nt * 8 + g];
#pragma unroll
                    for (int mt = 0; mt < 2; mt++) {
                        asm volatile(
                            "mma.sync.aligned.m16n8k8.row.col.f32.tf32.tf32.f32 "
                            "{%0,%1,%2,%3}, {%4,%5,%6,%7}, {%8,%9}, {%0,%1,%2,%3};"
                            : "+f"(o[mt][nt][0]), "+f"(o[mt][nt][1]),
                              "+f"(o[mt][nt][2]), "+f"(o[mt][nt][3])
                            : "r"(a[mt][0]), "r"(a[mt][1]), "r"(a[mt][2]), "r"(a[mt][3]),
                              "r"(b0), "r"(b1));
                    }
                }
            }
        }
        __syncthreads();

        if (kt + 2 < ntiles) {
            const int kn = (kt + 2) * ATT_BK;
            float* kd = k_s + (kt & 1) * ATT_BK * KSTR;
            float* vd = v_s + (kt & 1) * ATT_BK * VST2;
#pragma unroll
            for (int i = 0; i < 4; i++) {
                int idx = tid + i * 256;
                int row = idx >> 4, c4 = (idx & 15) << 2;
                cpasync16(&kd[row * KSTR + c4], &K[(kn + row) * (NKV * HD) + kvh * HD + c4]);
                cpasync16(&vd[row * VST2 + c4], &V[(kn + row) * (NKV * HD) + kvh * HD + c4]);
            }
            cp_commit();
        }
    }

    // ---- epilogue: normalize + sink scale; write tf32-rounded O ----
    float snk = sinks[h];
#pragma unroll
    for (int mt = 0; mt < 2; mt++) {
        int qa = q0 + mw + mt * 16 + g;
        int qb = qa + 8;
        float lseA = (m_st[mt][0] + __log2f(l_st[mt][0])) * LN2;
        float lseB = (m_st[mt][1] + __log2f(l_st[mt][1])) * LN2;
        float invA = (1.f / (1.f + __expf(-(lseA - snk)))) / l_st[mt][0];
        float invB = (1.f / (1.f + __expf(-(lseB - snk)))) / l_st[mt][1];
#pragma unroll
        for (int nt = 0; nt < 8; nt++) {
            int col = nt * 8 + 2 * t;
            *(float2*)&O[qa * (NH * HD) + h * HD + col] =
                make_float2(ftf(o[mt][nt][0] * invA), ftf(o[mt][nt][1] * invA));
            *(float2*)&O[qb * (NH * HD) + h * HD + col] =
                make_float2(ftf(o[mt][nt][2] * invB), ftf(o[mt][nt][3] * invB));
        }
    }
}

// ---------------- launch ----------------------------------------------------
extern "C" void kernel_launch(void* const* d_in, const int* in_sizes, int n_in,
                              void* d_out, int out_size)
{
    const float* x     = (const float*)d_in[0];
    const float* rope  = (const float*)d_in[1];
    const float* wq_w  = (const float*)d_in[2];
    const float* wq_b  = (const float*)d_in[3];
    const float* wk_w  = (const float*)d_in[4];
    const float* wk_b  = (const float*)d_in[5];
    const float* wv_w  = (const float*)d_in[6];
    const float* wv_b  = (const float*)d_in[7];
    const float* wo_w  = (const float*)d_in[8];
    const float* wo_b  = (const float*)d_in[9];
    const float* sinks = (const float*)d_in[10];
    float* out = (float*)d_out;

    float *gq, *gk, *gv, *ga, *gx;
    cudaGetSymbolAddress((void**)&gq, g_q);
    cudaGetSymbolAddress((void**)&gk, g_k);
    cudaGetSymbolAddress((void**)&gv, g_v);
    cudaGetSymbolAddress((void**)&ga, g_attn);
    cudaGetSymbolAddress((void**)&gx, g_x);

    cudaFuncSetAttribute(qkv_gemm, cudaFuncAttributeMaxDynamicSharedMemorySize,
                         GEMM_SMEM);
    cudaFuncSetAttribute(gemm2, cudaFuncAttributeMaxDynamicSharedMemorySize,
                         GEMM_SMEM);
    cudaFuncSetAttribute(attn_mma, cudaFuncAttributeMaxDynamicSharedMemorySize,
                         ATT_SMEM);

    // tf32 round-copy of x -> CVT-free A-side in qkv_gemm
    const int n4 = (S_LEN * DIM) / 4;
    round_copy<<<(n4 + 255) / 256, 256>>>(x, gx, n4);

    // Fused QKV projections + RoPE (Q pre-scaled for exp2 softmax)
    qkv_gemm<<<dim3(24, 16), 256, GEMM_SMEM>>>(gx, rope,
                                               wq_w, wq_b, gq,
                                               wk_w, wk_b, gk,
                                               wv_w, wv_b, gv);

    // Flash attention (exp2 softmax, CVT-free mma, heavy-first, rounded O)
    attn_mma<<<dim3(S_LEN / ATT_BQ, NH), 256, ATT_SMEM>>>(gq, gk, gv, sinks, ga);

    // Output projection (A = g_attn pre-rounded -> CVT-free A-side)
    gemm2<<<dim3(16, 16), 256, GEMM_SMEM>>>(ga, wo_w, wo_b, out, DIM, NH * HD);
}